// round 3
// baseline (speedup 1.0000x reference)
#include <cuda_runtime.h>
#include <math.h>
#include <stdint.h>

// Problem constants
#define B_  32
#define T_  64
#define P_  196
#define D_  768
#define H_  12
#define HD_ 64

// ---------------- scratch (static device globals; no allocations) ----------------
__device__ float g_q   [B_*T_*D_];
__device__ float g_k   [B_*P_*D_];
__device__ float g_v   [B_*P_*D_];
__device__ float g_attn[B_*T_*D_];
__device__ float g_upd [B_*T_*D_];
__device__ float g_wht [B_*T_*D_];
__device__ float g_whi [B_*P_*D_];
__device__ float g_src_t[B_*T_*H_], g_dst_t[B_*T_*H_];
__device__ float g_src_i[B_*P_*H_], g_dst_i[B_*P_*H_];
__device__ float g_att_t[B_*H_*T_*T_];
__device__ float g_att_i[B_*H_*P_*P_];
__device__ float g_tgf[B_*D_], g_igf[B_*D_], g_ftok[B_*D_], g_fglob[B_*D_];
__device__ float g_stok[B_], g_sphr[B_], g_sglob[B_];

// ---------------- utility ----------------
__global__ void zero2_kernel(float* a, float* b, int n) {
    int i = blockIdx.x * blockDim.x + threadIdx.x;
    if (i < n) { a[i] = 0.f; b[i] = 0.f; }
}

// ---------------- SGEMM: C[M,N] = A[M,K] @ B[K,N] (+bias) ----------------
// 128x128 tile, K-step 8, 256 threads, 8x8 micro-tile. Requires M%128==0,
// N%128==0, K%8==0 (true for every call here).
__global__ __launch_bounds__(256, 2)
void sgemm_kernel(const float* __restrict__ A, const float* __restrict__ Bm,
                  const float* __restrict__ bias, float* __restrict__ C,
                  int M, int N, int K) {
    __shared__ float As[8][128];
    __shared__ float Bs[8][128];
    int tid = threadIdx.x;
    int m0 = blockIdx.y * 128, n0 = blockIdx.x * 128;
    int tx = tid & 15, ty = tid >> 4;
    int arow = tid >> 1, acol = (tid & 1) * 4;
    int brow = tid >> 5, bcol = (tid & 31) * 4;
    const float* Ap = A + (size_t)(m0 + arow) * K + acol;
    const float* Bp = Bm + (size_t)brow * N + n0 + bcol;

    float acc[8][8];
#pragma unroll
    for (int i = 0; i < 8; i++)
#pragma unroll
        for (int j = 0; j < 8; j++) acc[i][j] = 0.f;

    int nk = K >> 3;
    for (int kt = 0; kt < nk; kt++) {
        float4 av = *(const float4*)Ap;
        float4 bv = *(const float4*)Bp;
        As[acol + 0][arow] = av.x;
        As[acol + 1][arow] = av.y;
        As[acol + 2][arow] = av.z;
        As[acol + 3][arow] = av.w;
        *(float4*)&Bs[brow][bcol] = bv;
        __syncthreads();
#pragma unroll
        for (int k = 0; k < 8; k++) {
            float4 a0 = *(const float4*)&As[k][ty * 8];
            float4 a1 = *(const float4*)&As[k][ty * 8 + 4];
            float4 b0 = *(const float4*)&Bs[k][tx * 8];
            float4 b1 = *(const float4*)&Bs[k][tx * 8 + 4];
            float ar[8] = {a0.x, a0.y, a0.z, a0.w, a1.x, a1.y, a1.z, a1.w};
            float br[8] = {b0.x, b0.y, b0.z, b0.w, b1.x, b1.y, b1.z, b1.w};
#pragma unroll
            for (int i = 0; i < 8; i++)
#pragma unroll
                for (int j = 0; j < 8; j++) acc[i][j] += ar[i] * br[j];
        }
        __syncthreads();
        Ap += 8;
        Bp += (size_t)8 * N;
    }

    float breg[8];
#pragma unroll
    for (int j = 0; j < 8; j++) breg[j] = bias ? bias[n0 + tx * 8 + j] : 0.f;
#pragma unroll
    for (int i = 0; i < 8; i++) {
        float* Crow = C + (size_t)(m0 + ty * 8 + i) * N + n0 + tx * 8;
        float4 v0 = make_float4(acc[i][0] + breg[0], acc[i][1] + breg[1],
                                acc[i][2] + breg[2], acc[i][3] + breg[3]);
        float4 v1 = make_float4(acc[i][4] + breg[4], acc[i][5] + breg[5],
                                acc[i][6] + breg[6], acc[i][7] + breg[7]);
        *(float4*)Crow = v0;
        *(float4*)(Crow + 4) = v1;
    }
}

// ---------------- cross attention: per (b,h), K/V resident in smem ----------------
#define ATTN_SMEM (2 * P_ * 65 * 4)
__global__ void attn_kernel(const float* __restrict__ q, const float* __restrict__ k,
                            const float* __restrict__ v, float* __restrict__ out) {
    int h = blockIdx.x, b = blockIdx.y;
    extern __shared__ float sm[];
    float* Ks = sm;             // [P_][65]
    float* Vs = sm + P_ * 65;   // [P_][65]
    __shared__ float qs[HD_];
    __shared__ float red[256];
    __shared__ float wbuf[256];
    __shared__ float part[256];
    int tid = threadIdx.x;

    for (int idx = tid; idx < P_ * HD_; idx += 256) {
        int p = idx >> 6, d = idx & 63;
        size_t g = (size_t)(b * P_ + p) * D_ + h * HD_ + d;
        Ks[p * 65 + d] = k[g];
        Vs[p * 65 + d] = v[g];
    }
    __syncthreads();

    for (int t = 0; t < T_; t++) {
        if (tid < HD_) qs[tid] = q[(size_t)(b * T_ + t) * D_ + h * HD_ + tid];
        __syncthreads();
        float s = -1e30f;
        if (tid < P_) {
            float a = 0.f;
#pragma unroll
            for (int d = 0; d < HD_; d++) a += qs[d] * Ks[tid * 65 + d];
            s = a * 0.125f;  // 1/sqrt(64)
        }
        red[tid] = s;
        __syncthreads();
        for (int o = 128; o; o >>= 1) {
            if (tid < o) red[tid] = fmaxf(red[tid], red[tid + o]);
            __syncthreads();
        }
        float m = red[0];
        __syncthreads();
        float e = (tid < P_) ? expf(s - m) : 0.f;
        wbuf[tid] = e;
        red[tid] = e;
        __syncthreads();
        for (int o = 128; o; o >>= 1) {
            if (tid < o) red[tid] += red[tid + o];
            __syncthreads();
        }
        float Z = red[0];
        int d = tid & 63, g = tid >> 6;
        float a = 0.f;
        for (int p = g; p < P_; p += 4) a += wbuf[p] * Vs[p * 65 + d];
        part[tid] = a;
        __syncthreads();
        if (tid < HD_) {
            float o = (part[tid] + part[tid + 64] + part[tid + 128] + part[tid + 192]) / Z;
            out[(size_t)(b * T_ + t) * D_ + h * HD_ + tid] = o;
        }
        __syncthreads();
    }
}

// ---------------- GAT: src/dst projections ----------------
__global__ void gat_srcdst_kernel(const float* __restrict__ Wh, const float* __restrict__ a,
                                  float* __restrict__ src, float* __restrict__ dst, int N) {
    int h = blockIdx.x, n = blockIdx.y, b = blockIdx.z;
    int f = threadIdx.x;  // 64
    float w = Wh[(size_t)(b * N + n) * D_ + h * 64 + f];
    __shared__ float r1[64], r2[64];
    r1[f] = w * a[f];
    r2[f] = w * a[64 + f];
    __syncthreads();
    for (int o = 32; o; o >>= 1) {
        if (f < o) { r1[f] += r1[f + o]; r2[f] += r2[f + o]; }
        __syncthreads();
    }
    if (f == 0) {
        src[(b * N + n) * H_ + h] = r1[0];
        dst[(b * N + n) * H_ + h] = r2[0];
    }
}

// ---------------- GAT: masked-softmax attention rows ----------------
__global__ void gat_att_kernel(const float* __restrict__ src, const float* __restrict__ dst,
                               const int* __restrict__ adj, int adjBatchStride,
                               float* __restrict__ att, int N) {
    int i = blockIdx.x, h = blockIdx.y, b = blockIdx.z;
    int tid = threadIdx.x;  // 256
    __shared__ float red[256];
    bool valid = false;
    float val = -1e30f;
    if (tid < N) {
        int a = adj[(size_t)b * adjBatchStride + i * N + tid];
        if (a > 0) {
            valid = true;
            float e = src[(b * N + i) * H_ + h] + dst[(b * N + tid) * H_ + h];
            val = e > 0.f ? e : 0.2f * e;  // leaky_relu 0.2
        }
    }
    red[tid] = val;
    __syncthreads();
    for (int o = 128; o; o >>= 1) {
        if (tid < o) red[tid] = fmaxf(red[tid], red[tid + o]);
        __syncthreads();
    }
    float m = red[0];
    __syncthreads();
    float e = valid ? expf(val - m) : 0.f;
    red[tid] = e;
    __syncthreads();
    for (int o = 128; o; o >>= 1) {
        if (tid < o) red[tid] += red[tid + o];
        __syncthreads();
    }
    float Z = red[0];
    if (tid < N)
        att[(((size_t)(b * H_ + h) * N) + i) * N + tid] = e / Z;
}

// ---------------- GAT: aggregation + ELU + mean (atomic accumulate) ----------------
template <int N, int ITILE>
__global__ void gat_agg_kernel(const float* __restrict__ Wh, const float* __restrict__ att,
                               float* __restrict__ outmean) {
    int tile = blockIdx.x, h = blockIdx.y, b = blockIdx.z;
    int i0 = tile * ITILE;
    extern __shared__ float sm[];
    float* Whs = sm;            // [N][64]
    float* atts = sm + N * 64;  // [ITILE][N]
    __shared__ float red[256];
    int tid = threadIdx.x;

    for (int idx = tid; idx < N * 64; idx += 256) {
        int j = idx >> 6, f = idx & 63;
        Whs[idx] = Wh[(size_t)(b * N + j) * D_ + h * 64 + f];
    }
    for (int idx = tid; idx < ITILE * N; idx += 256) {
        int ii = idx / N, j = idx - ii * N;
        atts[idx] = att[(((size_t)(b * H_ + h) * N) + i0 + ii) * N + j];
    }
    __syncthreads();

    int f = tid & 63, g = tid >> 6;
    for (int ii = 0; ii < ITILE; ii++) {
        float acc = 0.f;
        for (int j = g; j < N; j += 4) acc += atts[ii * N + j] * Whs[j * 64 + f];
        red[tid] = acc;
        __syncthreads();
        if (tid < 64) {
            float s = red[tid] + red[tid + 64] + red[tid + 128] + red[tid + 192];
            s = s > 0.f ? s : expm1f(s);  // ELU
            atomicAdd(&outmean[b * D_ + h * 64 + tid], s * (1.0f / N));
        }
        __syncthreads();
    }
}

// ---------------- token fusion: f_token, s_token ----------------
__global__ void token_kernel(const float* __restrict__ upd, const float* __restrict__ img,
                             float* __restrict__ ftok, float* __restrict__ stok) {
    int b = blockIdx.x, tid = threadIdx.x;  // 256
    for (int d = tid; d < D_; d += 256) {
        float s = 0.f;
        for (int t = 0; t < T_; t++) s += upd[(size_t)(b * T_ + t) * D_ + d];
        ftok[b * D_ + d] = s * (1.0f / T_);
    }
    float acc = 0.f;
    for (int t = 0; t < T_; t++)
        for (int d = tid; d < D_; d += 256)
            acc += upd[(size_t)(b * T_ + t) * D_ + d] * img[(size_t)(b * P_ + t) * D_ + d];
    __shared__ float red[256];
    red[tid] = acc;
    __syncthreads();
    for (int o = 128; o; o >>= 1) {
        if (tid < o) red[tid] += red[tid + o];
        __syncthreads();
    }
    if (tid == 0) stok[b] = red[0] * (1.0f / T_);
}

// ---------------- f_global = clip_text @ Wp + bp ----------------
__global__ void fglobal_kernel(const float* __restrict__ ct, const float* __restrict__ Wp,
                               const float* __restrict__ bp, float* __restrict__ out) {
    int b = blockIdx.y;
    int n = blockIdx.x * 128 + threadIdx.x;
    float acc = bp[n];
    for (int k = 0; k < 512; k++) acc += ct[b * 512 + k] * Wp[(size_t)k * D_ + n];
    out[b * D_ + n] = acc;
}

// ---------------- cosine scores ----------------
__global__ void cos_kernel(const float* __restrict__ tgf, const float* __restrict__ igf,
                           const float* __restrict__ ct, const float* __restrict__ ci,
                           const float* __restrict__ ls,
                           float* __restrict__ sphr, float* __restrict__ sglob) {
    int b = blockIdx.x, tid = threadIdx.x;  // 256
    __shared__ float r0[256], r1[256], r2[256];
    float d0 = 0.f, d1 = 0.f, d2 = 0.f;
    for (int d = tid; d < D_; d += 256) {
        float x = tgf[b * D_ + d], y = igf[b * D_ + d];
        d0 += x * y; d1 += x * x; d2 += y * y;
    }
    r0[tid] = d0; r1[tid] = d1; r2[tid] = d2;
    __syncthreads();
    for (int o = 128; o; o >>= 1) {
        if (tid < o) { r0[tid] += r0[tid + o]; r1[tid] += r1[tid + o]; r2[tid] += r2[tid + o]; }
        __syncthreads();
    }
    if (tid == 0) {
        float nx = fmaxf(sqrtf(r1[0]), 1e-8f), ny = fmaxf(sqrtf(r2[0]), 1e-8f);
        sphr[b] = r0[0] / (nx * ny);
    }
    __syncthreads();
    d0 = d1 = d2 = 0.f;
    for (int d = tid; d < 512; d += 256) {
        float x = ct[b * 512 + d], y = ci[b * 512 + d];
        d0 += x * y; d1 += x * x; d2 += y * y;
    }
    r0[tid] = d0; r1[tid] = d1; r2[tid] = d2;
    __syncthreads();
    for (int o = 128; o; o >>= 1) {
        if (tid < o) { r0[tid] += r0[tid + o]; r1[tid] += r1[tid + o]; r2[tid] += r2[tid + o]; }
        __syncthreads();
    }
    if (tid == 0) {
        float nx = fmaxf(sqrtf(r1[0]), 1e-8f), ny = fmaxf(sqrtf(r2[0]), 1e-8f);
        sglob[b] = expf(*ls) * r0[0] / (nx * ny);
    }
}

// ---------------- fusion head -> logits ----------------
__global__ void head_kernel(const float* __restrict__ stok, const float* __restrict__ sphr,
                            const float* __restrict__ sglob,
                            const float* __restrict__ f1w, const float* __restrict__ f1b,
                            const float* __restrict__ f2w, const float* __restrict__ f2b,
                            const float* __restrict__ ftok, const float* __restrict__ tgf,
                            const float* __restrict__ fglob,
                            const float* __restrict__ c1w, const float* __restrict__ c1b,
                            const float* __restrict__ c2w, const float* __restrict__ c2b,
                            float* __restrict__ out) {
    int b = blockIdx.x, tid = threadIdx.x;  // 384
    __shared__ float w3[3];
    __shared__ float fa[D_];
    __shared__ float red[768];
    if (tid == 0) {
        float s3[3] = {stok[b], sphr[b], sglob[b]};
        float h16[16];
        for (int j = 0; j < 16; j++) {
            float v = f1b[j];
            for (int i = 0; i < 3; i++) v += s3[i] * f1w[i * 16 + j];
            h16[j] = 0.5f * v * (1.0f + erff(v * 0.70710678118654752f));  // exact gelu
        }
        for (int c = 0; c < 3; c++) {
            float v = f2b[c];
            for (int j = 0; j < 16; j++) v += h16[j] * f2w[j * 3 + c];
            w3[c] = 1.0f / (1.0f + expf(-v));
        }
    }
    __syncthreads();
    for (int d = tid; d < D_; d += 384)
        fa[d] = w3[0] * ftok[b * D_ + d] + w3[1] * tgf[b * D_ + d] + w3[2] * fglob[b * D_ + d];
    __syncthreads();
    float hj = c1b[tid];
    for (int d = 0; d < D_; d++) hj += fa[d] * c1w[(size_t)d * 384 + tid];
    hj = fmaxf(hj, 0.f);
    red[tid] = hj * c2w[tid * 2];
    red[384 + tid] = hj * c2w[tid * 2 + 1];
    __syncthreads();
    if (tid < 128) {  // collapse 384 -> 128
        red[tid] += red[tid + 128] + red[tid + 256];
        red[384 + tid] += red[384 + tid + 128] + red[384 + tid + 256];
    }
    __syncthreads();
    for (int o = 64; o; o >>= 1) {
        if (tid < o) { red[tid] += red[tid + o]; red[384 + tid] += red[384 + tid + o]; }
        __syncthreads();
    }
    if (tid == 0) {
        out[b * 2 + 0] = red[0] + c2b[0];
        out[b * 2 + 1] = red[384] + c2b[1];
    }
}

// ---------------- host launcher ----------------
extern "C" void kernel_launch(void* const* d_in, const int* in_sizes, int n_in,
                              void* d_out, int out_size) {
    const float* text       = (const float*)d_in[0];
    const float* image      = (const float*)d_in[1];
    const float* clip_text  = (const float*)d_in[2];
    const float* clip_image = (const float*)d_in[3];
    const float* logit_sc   = (const float*)d_in[4];
    const float* wq = (const float*)d_in[5];  const float* bq = (const float*)d_in[6];
    const float* wk = (const float*)d_in[7];  const float* bk = (const float*)d_in[8];
    const float* wv = (const float*)d_in[9];  const float* bv = (const float*)d_in[10];
    const float* wo = (const float*)d_in[11]; const float* bo = (const float*)d_in[12];
    const float* Wt = (const float*)d_in[13]; const float* at = (const float*)d_in[14];
    const float* Wi = (const float*)d_in[15]; const float* ai = (const float*)d_in[16];
    const float* Wp = (const float*)d_in[17]; const float* bp = (const float*)d_in[18];
    const float* f1w = (const float*)d_in[19]; const float* f1b = (const float*)d_in[20];
    const float* f2w = (const float*)d_in[21]; const float* f2b = (const float*)d_in[22];
    const float* c1w = (const float*)d_in[23]; const float* c1b = (const float*)d_in[24];
    const float* c2w = (const float*)d_in[25]; const float* c2b = (const float*)d_in[26];
    const int* text_adj  = (const int*)d_in[27];
    const int* image_adj = (const int*)d_in[28];
    float* out = (float*)d_out;

    float *p_q, *p_k, *p_v, *p_attn, *p_upd, *p_wht, *p_whi;
    float *p_src_t, *p_dst_t, *p_src_i, *p_dst_i, *p_att_t, *p_att_i;
    float *p_tgf, *p_igf, *p_ftok, *p_fglob, *p_stok, *p_sphr, *p_sglob;
    cudaGetSymbolAddress((void**)&p_q, g_q);
    cudaGetSymbolAddress((void**)&p_k, g_k);
    cudaGetSymbolAddress((void**)&p_v, g_v);
    cudaGetSymbolAddress((void**)&p_attn, g_attn);
    cudaGetSymbolAddress((void**)&p_upd, g_upd);
    cudaGetSymbolAddress((void**)&p_wht, g_wht);
    cudaGetSymbolAddress((void**)&p_whi, g_whi);
    cudaGetSymbolAddress((void**)&p_src_t, g_src_t);
    cudaGetSymbolAddress((void**)&p_dst_t, g_dst_t);
    cudaGetSymbolAddress((void**)&p_src_i, g_src_i);
    cudaGetSymbolAddress((void**)&p_dst_i, g_dst_i);
    cudaGetSymbolAddress((void**)&p_att_t, g_att_t);
    cudaGetSymbolAddress((void**)&p_att_i, g_att_i);
    cudaGetSymbolAddress((void**)&p_tgf, g_tgf);
    cudaGetSymbolAddress((void**)&p_igf, g_igf);
    cudaGetSymbolAddress((void**)&p_ftok, g_ftok);
    cudaGetSymbolAddress((void**)&p_fglob, g_fglob);
    cudaGetSymbolAddress((void**)&p_stok, g_stok);
    cudaGetSymbolAddress((void**)&p_sphr, g_sphr);
    cudaGetSymbolAddress((void**)&p_sglob, g_sglob);

    cudaFuncSetAttribute(attn_kernel, cudaFuncAttributeMaxDynamicSharedMemorySize, ATTN_SMEM);
    int aggI_smem = (P_ * 64 + 14 * P_) * 4;  // 61152 B
    cudaFuncSetAttribute(gat_agg_kernel<P_, 14>, cudaFuncAttributeMaxDynamicSharedMemorySize, aggI_smem);
    int aggT_smem = (T_ * 64 + 16 * T_) * 4;  // 20480 B

    // zero the GAT mean accumulators
    zero2_kernel<<<(B_ * D_ + 255) / 256, 256>>>(p_tgf, p_igf, B_ * D_);

    // projections
    sgemm_kernel<<<dim3(6, 16), 256>>>(text, wq, bq, p_q, B_ * T_, D_, D_);
    sgemm_kernel<<<dim3(6, 49), 256>>>(image, wk, bk, p_k, B_ * P_, D_, D_);
    sgemm_kernel<<<dim3(6, 49), 256>>>(image, wv, bv, p_v, B_ * P_, D_, D_);
    sgemm_kernel<<<dim3(6, 16), 256>>>(text, Wt, nullptr, p_wht, B_ * T_, D_, D_);
    sgemm_kernel<<<dim3(6, 49), 256>>>(image, Wi, nullptr, p_whi, B_ * P_, D_, D_);

    // cross attention + output projection
    attn_kernel<<<dim3(H_, B_), 256, ATTN_SMEM>>>(p_q, p_k, p_v, p_attn);
    sgemm_kernel<<<dim3(6, 16), 256>>>(p_attn, wo, bo, p_upd, B_ * T_, D_, D_);

    // GATs
    gat_srcdst_kernel<<<dim3(H_, T_, B_), 64>>>(p_wht, at, p_src_t, p_dst_t, T_);
    gat_srcdst_kernel<<<dim3(H_, P_, B_), 64>>>(p_whi, ai, p_src_i, p_dst_i, P_);
    gat_att_kernel<<<dim3(T_, H_, B_), 256>>>(p_src_t, p_dst_t, text_adj, T_ * T_, p_att_t, T_);
    gat_att_kernel<<<dim3(P_, H_, B_), 256>>>(p_src_i, p_dst_i, image_adj, 0, p_att_i, P_);
    gat_agg_kernel<T_, 16><<<dim3(4, H_, B_), 256, aggT_smem>>>(p_wht, p_att_t, p_tgf);
    gat_agg_kernel<P_, 14><<<dim3(14, H_, B_), 256, aggI_smem>>>(p_whi, p_att_i, p_igf);

    // scalar scores + global feature
    token_kernel<<<B_, 256>>>(p_upd, image, p_ftok, p_stok);
    fglobal_kernel<<<dim3(6, B_), 128>>>(clip_text, Wp, bp, p_fglob);
    cos_kernel<<<B_, 256>>>(p_tgf, p_igf, clip_text, clip_image, logit_sc, p_sphr, p_sglob);

    // fusion head
    head_kernel<<<B_, 384>>>(p_stok, p_sphr, p_sglob, f1w, f1b, f2w, f2b,
                             p_ftok, p_tgf, p_fglob, c1w, c1b, c2w, c2b, out);
}

// round 4
// speedup vs baseline: 1.7799x; 1.7799x over previous
#include <cuda_runtime.h>
#include <math.h>
#include <stdint.h>

// Problem constants
#define B_  32
#define T_  64
#define P_  196
#define D_  768
#define H_  12
#define HD_ 64

// ---------------- scratch (static device globals; no allocations) ----------------
__device__ float g_q   [B_*T_*D_];
__device__ float g_k   [B_*P_*D_];
__device__ float g_v   [B_*P_*D_];
__device__ float g_attn[B_*T_*D_];
__device__ float g_upd [B_*T_*D_];
__device__ float g_wht [B_*T_*D_];
__device__ float g_whi [B_*P_*D_];
__device__ float g_tgf[B_*D_], g_igf[B_*D_], g_ftok[B_*D_], g_fglob[B_*D_];
__device__ float g_stok[B_], g_sphr[B_], g_sglob[B_];

// ---------------- utility ----------------
__global__ void zero3_kernel(float* a, float* b, float* c, int n, int nc) {
    int i = blockIdx.x * blockDim.x + threadIdx.x;
    if (i < n) { a[i] = 0.f; b[i] = 0.f; }
    if (i < nc) c[i] = 0.f;
}

// ---------------- SGEMM: C[M,N] = A[M,K] @ B[K,N] (+bias) ----------------
// 128x128 tile, K-step 8, 256 threads, 8x8 micro-tile, double-buffered smem.
// Requires M%128==0, N%128==0, K%8==0 (true for every call here).
__global__ __launch_bounds__(256, 2)
void sgemm_kernel(const float* __restrict__ A, const float* __restrict__ Bm,
                  const float* __restrict__ bias, float* __restrict__ C,
                  int M, int N, int K) {
    __shared__ float As[2][8][128];
    __shared__ float Bs[2][8][128];
    int tid = threadIdx.x;
    int m0 = blockIdx.y * 128, n0 = blockIdx.x * 128;
    int tx = tid & 15, ty = tid >> 4;
    int arow = tid >> 1, acol = (tid & 1) * 4;
    int brow = tid >> 5, bcol = (tid & 31) * 4;
    const float* Ap = A + (size_t)(m0 + arow) * K + acol;
    const float* Bp = Bm + (size_t)brow * N + n0 + bcol;

    float acc[8][8];
#pragma unroll
    for (int i = 0; i < 8; i++)
#pragma unroll
        for (int j = 0; j < 8; j++) acc[i][j] = 0.f;

    float4 av = *(const float4*)Ap;
    float4 bv = *(const float4*)Bp;
    As[0][acol + 0][arow] = av.x;
    As[0][acol + 1][arow] = av.y;
    As[0][acol + 2][arow] = av.z;
    As[0][acol + 3][arow] = av.w;
    *(float4*)&Bs[0][brow][bcol] = bv;
    __syncthreads();

    int nk = K >> 3;
    int cur = 0;
    for (int kt = 1; kt < nk; kt++) {
        Ap += 8;
        Bp += (size_t)8 * N;
        av = *(const float4*)Ap;   // prefetch next tile
        bv = *(const float4*)Bp;
#pragma unroll
        for (int k = 0; k < 8; k++) {
            float4 a0 = *(const float4*)&As[cur][k][ty * 8];
            float4 a1 = *(const float4*)&As[cur][k][ty * 8 + 4];
            float4 b0 = *(const float4*)&Bs[cur][k][tx * 8];
            float4 b1 = *(const float4*)&Bs[cur][k][tx * 8 + 4];
            float ar[8] = {a0.x, a0.y, a0.z, a0.w, a1.x, a1.y, a1.z, a1.w};
            float br[8] = {b0.x, b0.y, b0.z, b0.w, b1.x, b1.y, b1.z, b1.w};
#pragma unroll
            for (int i = 0; i < 8; i++)
#pragma unroll
                for (int j = 0; j < 8; j++) acc[i][j] += ar[i] * br[j];
        }
        int nxt = cur ^ 1;
        As[nxt][acol + 0][arow] = av.x;
        As[nxt][acol + 1][arow] = av.y;
        As[nxt][acol + 2][arow] = av.z;
        As[nxt][acol + 3][arow] = av.w;
        *(float4*)&Bs[nxt][brow][bcol] = bv;
        __syncthreads();
        cur = nxt;
    }
    // last tile
#pragma unroll
    for (int k = 0; k < 8; k++) {
        float4 a0 = *(const float4*)&As[cur][k][ty * 8];
        float4 a1 = *(const float4*)&As[cur][k][ty * 8 + 4];
        float4 b0 = *(const float4*)&Bs[cur][k][tx * 8];
        float4 b1 = *(const float4*)&Bs[cur][k][tx * 8 + 4];
        float ar[8] = {a0.x, a0.y, a0.z, a0.w, a1.x, a1.y, a1.z, a1.w};
        float br[8] = {b0.x, b0.y, b0.z, b0.w, b1.x, b1.y, b1.z, b1.w};
#pragma unroll
        for (int i = 0; i < 8; i++)
#pragma unroll
            for (int j = 0; j < 8; j++) acc[i][j] += ar[i] * br[j];
    }

    float breg[8];
#pragma unroll
    for (int j = 0; j < 8; j++) breg[j] = bias ? bias[n0 + tx * 8 + j] : 0.f;
#pragma unroll
    for (int i = 0; i < 8; i++) {
        float* Crow = C + (size_t)(m0 + ty * 8 + i) * N + n0 + tx * 8;
        float4 v0 = make_float4(acc[i][0] + breg[0], acc[i][1] + breg[1],
                                acc[i][2] + breg[2], acc[i][3] + breg[3]);
        float4 v1 = make_float4(acc[i][4] + breg[4], acc[i][5] + breg[5],
                                acc[i][6] + breg[6], acc[i][7] + breg[7]);
        *(float4*)Crow = v0;
        *(float4*)(Crow + 4) = v1;
    }
}

// ---------------- cross attention: per (b,h); warp-per-2-timesteps ----------------
#define KV_STRIDE 66
#define ATTN_SMEM ((2 * P_ * KV_STRIDE + 8 * 132) * 4)
__global__ void attn_kernel(const float* __restrict__ q, const float* __restrict__ k,
                            const float* __restrict__ v, float* __restrict__ out) {
    int h = blockIdx.x, b = blockIdx.y;
    extern __shared__ float sm[];
    float* Ks = sm;                       // [P_][66]
    float* Vs = Ks + P_ * KV_STRIDE;      // [P_][66]
    float* qs = Vs + P_ * KV_STRIDE;      // [8 warps][2*66]
    int tid = threadIdx.x, lane = tid & 31, w = tid >> 5;

    for (int idx = tid; idx < P_ * 64; idx += 256) {
        int p = idx >> 6, d = idx & 63;
        size_t g = (size_t)(b * P_ + p) * D_ + h * 64 + d;
        Ks[p * KV_STRIDE + d] = k[g];
        Vs[p * KV_STRIDE + d] = v[g];
    }
    __syncthreads();

    float* myq = qs + w * 132;
    int ro[7];
#pragma unroll
    for (int r = 0; r < 7; r++) {
        int p = lane + 32 * r;
        ro[r] = (p < P_ ? p : P_ - 1) * KV_STRIDE;
    }

    for (int s = 0; s < 4; s++) {
        int t0 = w * 8 + s * 2;
        __syncwarp();
        myq[lane]       = q[(size_t)(b * T_ + t0) * D_ + h * 64 + lane];
        myq[lane + 32]  = q[(size_t)(b * T_ + t0) * D_ + h * 64 + lane + 32];
        myq[66 + lane]      = q[(size_t)(b * T_ + t0 + 1) * D_ + h * 64 + lane];
        myq[66 + lane + 32] = q[(size_t)(b * T_ + t0 + 1) * D_ + h * 64 + lane + 32];
        __syncwarp();

        float acc[2][7];
#pragma unroll
        for (int r = 0; r < 7; r++) { acc[0][r] = 0.f; acc[1][r] = 0.f; }
        for (int d = 0; d < 64; d++) {
            float q0 = myq[d], q1 = myq[66 + d];
#pragma unroll
            for (int r = 0; r < 7; r++) {
                float kv = Ks[ro[r] + d];
                acc[0][r] += q0 * kv;
                acc[1][r] += q1 * kv;
            }
        }

        float rZ[2];
#pragma unroll
        for (int tt = 0; tt < 2; tt++) {
            float m = -1e30f;
#pragma unroll
            for (int r = 0; r < 7; r++)
                if (lane + 32 * r < P_) m = fmaxf(m, acc[tt][r] * 0.125f);
#pragma unroll
            for (int o = 16; o; o >>= 1) m = fmaxf(m, __shfl_xor_sync(0xffffffffu, m, o));
            float Z = 0.f;
#pragma unroll
            for (int r = 0; r < 7; r++) {
                float wv = (lane + 32 * r < P_) ? expf(acc[tt][r] * 0.125f - m) : 0.f;
                acc[tt][r] = wv;
                Z += wv;
            }
#pragma unroll
            for (int o = 16; o; o >>= 1) Z += __shfl_xor_sync(0xffffffffu, Z, o);
            rZ[tt] = 1.f / Z;
        }

        float ov00 = 0.f, ov01 = 0.f, ov10 = 0.f, ov11 = 0.f;
#pragma unroll
        for (int r = 0; r < 6; r++) {
            int pl = 32 * r;
            for (int sl = 0; sl < 32; sl++) {
                float w0 = __shfl_sync(0xffffffffu, acc[0][r], sl);
                float w1 = __shfl_sync(0xffffffffu, acc[1][r], sl);
                float v0 = Vs[(pl + sl) * KV_STRIDE + lane];
                float v1 = Vs[(pl + sl) * KV_STRIDE + lane + 32];
                ov00 += w0 * v0; ov01 += w0 * v1;
                ov10 += w1 * v0; ov11 += w1 * v1;
            }
        }
        for (int sl = 0; sl < P_ - 192; sl++) {
            float w0 = __shfl_sync(0xffffffffu, acc[0][6], sl);
            float w1 = __shfl_sync(0xffffffffu, acc[1][6], sl);
            float v0 = Vs[(192 + sl) * KV_STRIDE + lane];
            float v1 = Vs[(192 + sl) * KV_STRIDE + lane + 32];
            ov00 += w0 * v0; ov01 += w0 * v1;
            ov10 += w1 * v0; ov11 += w1 * v1;
        }
        size_t o0 = (size_t)(b * T_ + t0) * D_ + h * 64 + lane;
        size_t o1 = (size_t)(b * T_ + t0 + 1) * D_ + h * 64 + lane;
        out[o0]      = ov00 * rZ[0];
        out[o0 + 32] = ov01 * rZ[0];
        out[o1]      = ov10 * rZ[1];
        out[o1 + 32] = ov11 * rZ[1];
    }
}

// ---------------- fully fused GAT: src/dst + masked softmax + agg + ELU + mean ----
// One block per (i-tile, h, b). Warp-per-row softmax (shfl only), then a
// register-tiled aggregation with Ws reads warp-broadcast.
template <int N, int ITILE>
__global__ void gat_fused_kernel(const float* __restrict__ Wh,
                                 const float* __restrict__ avec,
                                 const int* __restrict__ adj, int adjBatchStride,
                                 float* __restrict__ outmean) {
    constexpr int NPAD = 66;
    constexpr int NR = (N + 31) / 32;       // j-regs per lane in softmax
    constexpr int MI = (ITILE + 7) / 8;     // i's per thread in aggregation
    int tile = blockIdx.x, h = blockIdx.y, b = blockIdx.z;
    int i0 = tile * ITILE;
    extern __shared__ float sm[];
    float* Whs  = sm;                   // [N][66]
    float* Ws   = Whs + N * NPAD;       // [ITILE][N] unnormalized softmax weights
    float* srcs = Ws + ITILE * N;       // [N]
    float* dsts = srcs + N;             // [N]
    float* zinv = dsts + N;             // [ITILE]
    float* as   = zinv + ITILE;         // [128]
    int tid = threadIdx.x, lane = tid & 31, wid = tid >> 5;

    if (tid < 128) as[tid] = avec[tid];
    for (int idx = tid; idx < N * 64; idx += 256) {
        int j = idx >> 6, f = idx & 63;
        Whs[j * NPAD + f] = Wh[(size_t)(b * N + j) * D_ + h * 64 + f];
    }
    __syncthreads();

    // src/dst projections for all nodes (from smem)
    for (int j = tid; j < N; j += 256) {
        float s = 0.f, d = 0.f;
#pragma unroll 8
        for (int f = 0; f < 64; f++) {
            float wv = Whs[j * NPAD + f];
            s += wv * as[f];
            d += wv * as[64 + f];
        }
        srcs[j] = s;
        dsts[j] = d;
    }
    __syncthreads();

    // warp-per-row masked softmax, store unnormalized weights
    for (int iloc = wid; iloc < ITILE; iloc += 8) {
        int i = i0 + iloc;
        float si = srcs[i];
        float ev[NR];
        float m = -1e30f;
#pragma unroll
        for (int r = 0; r < NR; r++) {
            int j = lane + 32 * r;
            float e = -1e30f;
            if (j < N) {
                int a = adj[(size_t)b * adjBatchStride + (size_t)i * N + j];
                if (a > 0) {
                    float x = si + dsts[j];
                    e = x > 0.f ? x : 0.2f * x;
                }
            }
            ev[r] = e;
            m = fmaxf(m, e);
        }
#pragma unroll
        for (int o = 16; o; o >>= 1) m = fmaxf(m, __shfl_xor_sync(0xffffffffu, m, o));
        float Z = 0.f;
#pragma unroll
        for (int r = 0; r < NR; r++) {
            int j = lane + 32 * r;
            float wv = (ev[r] > -1e29f) ? expf(ev[r] - m) : 0.f;
            if (j < N) Ws[iloc * N + j] = wv;
            Z += wv;
        }
#pragma unroll
        for (int o = 16; o; o >>= 1) Z += __shfl_xor_sync(0xffffffffu, Z, o);
        if (lane == 0) zinv[iloc] = 1.f / Z;
    }
    __syncthreads();

    // aggregation: thread = (group wid, features f2,f2+1), i in {wid+8m}
    int f2 = lane * 2;
    float acc0[MI], acc1[MI];
#pragma unroll
    for (int m = 0; m < MI; m++) { acc0[m] = 0.f; acc1[m] = 0.f; }
    for (int j = 0; j < N; j++) {
        float2 wh = *(const float2*)&Whs[j * NPAD + f2];
#pragma unroll
        for (int m = 0; m < MI; m++) {
            int iloc = wid + 8 * m;
            float wv = (iloc < ITILE) ? Ws[iloc * N + j] : 0.f;  // warp-broadcast
            acc0[m] += wv * wh.x;
            acc1[m] += wv * wh.y;
        }
    }
    float s0 = 0.f, s1 = 0.f;
#pragma unroll
    for (int m = 0; m < MI; m++) {
        int iloc = wid + 8 * m;
        if (iloc < ITILE) {
            float z = zinv[iloc];
            float v0 = acc0[m] * z, v1 = acc1[m] * z;
            v0 = v0 > 0.f ? v0 : expm1f(v0);   // ELU
            v1 = v1 > 0.f ? v1 : expm1f(v1);
            s0 += v0;
            s1 += v1;
        }
    }
    atomicAdd(&outmean[b * D_ + h * 64 + f2],     s0 * (1.0f / N));
    atomicAdd(&outmean[b * D_ + h * 64 + f2 + 1], s1 * (1.0f / N));
}

// ---------------- f_token = mean_t upd ----------------
__global__ void ftok_kernel(const float* __restrict__ upd, float* __restrict__ ftok) {
    int idx = blockIdx.x * 256 + threadIdx.x;   // B*D
    int b = idx / D_, d = idx - b * D_;
    float s = 0.f;
    for (int t = 0; t < T_; t++) s += upd[(size_t)(b * T_ + t) * D_ + d];
    ftok[idx] = s * (1.0f / T_);
}

// ---------------- s_token: warp per (b,t) diag dot ----------------
__global__ void stok_kernel(const float* __restrict__ upd, const float* __restrict__ img,
                            float* __restrict__ stok) {
    int gw = (blockIdx.x * 256 + threadIdx.x) >> 5;   // 0..B*T-1
    int lane = threadIdx.x & 31;
    int b = gw >> 6, t = gw & 63;
    float a = 0.f;
    for (int d = lane; d < D_; d += 32)
        a += upd[(size_t)(b * T_ + t) * D_ + d] * img[(size_t)(b * P_ + t) * D_ + d];
#pragma unroll
    for (int o = 16; o; o >>= 1) a += __shfl_xor_sync(0xffffffffu, a, o);
    if (lane == 0) atomicAdd(&stok[b], a * (1.0f / T_));
}

// ---------------- f_global = clip_text @ Wp + bp ----------------
__global__ void fglobal_kernel(const float* __restrict__ ct, const float* __restrict__ Wp,
                               const float* __restrict__ bp, float* __restrict__ out) {
    int b = blockIdx.y;
    int n = blockIdx.x * 128 + threadIdx.x;
    float acc = bp[n];
    for (int k = 0; k < 512; k++) acc += ct[b * 512 + k] * Wp[(size_t)k * D_ + n];
    out[b * D_ + n] = acc;
}

// ---------------- cosine scores ----------------
__global__ void cos_kernel(const float* __restrict__ tgf, const float* __restrict__ igf,
                           const float* __restrict__ ct, const float* __restrict__ ci,
                           const float* __restrict__ ls,
                           float* __restrict__ sphr, float* __restrict__ sglob) {
    int b = blockIdx.x, tid = threadIdx.x;  // 256
    __shared__ float r0[256], r1[256], r2[256];
    float d0 = 0.f, d1 = 0.f, d2 = 0.f;
    for (int d = tid; d < D_; d += 256) {
        float x = tgf[b * D_ + d], y = igf[b * D_ + d];
        d0 += x * y; d1 += x * x; d2 += y * y;
    }
    r0[tid] = d0; r1[tid] = d1; r2[tid] = d2;
    __syncthreads();
    for (int o = 128; o; o >>= 1) {
        if (tid < o) { r0[tid] += r0[tid + o]; r1[tid] += r1[tid + o]; r2[tid] += r2[tid + o]; }
        __syncthreads();
    }
    if (tid == 0) {
        float nx = fmaxf(sqrtf(r1[0]), 1e-8f), ny = fmaxf(sqrtf(r2[0]), 1e-8f);
        sphr[b] = r0[0] / (nx * ny);
    }
    __syncthreads();
    d0 = d1 = d2 = 0.f;
    for (int d = tid; d < 512; d += 256) {
        float x = ct[b * 512 + d], y = ci[b * 512 + d];
        d0 += x * y; d1 += x * x; d2 += y * y;
    }
    r0[tid] = d0; r1[tid] = d1; r2[tid] = d2;
    __syncthreads();
    for (int o = 128; o; o >>= 1) {
        if (tid < o) { r0[tid] += r0[tid + o]; r1[tid] += r1[tid + o]; r2[tid] += r2[tid + o]; }
        __syncthreads();
    }
    if (tid == 0) {
        float nx = fmaxf(sqrtf(r1[0]), 1e-8f), ny = fmaxf(sqrtf(r2[0]), 1e-8f);
        sglob[b] = expf(*ls) * r0[0] / (nx * ny);
    }
}

// ---------------- fusion head -> logits ----------------
__global__ void head_kernel(const float* __restrict__ stok, const float* __restrict__ sphr,
                            const float* __restrict__ sglob,
                            const float* __restrict__ f1w, const float* __restrict__ f1b,
                            const float* __restrict__ f2w, const float* __restrict__ f2b,
                            const float* __restrict__ ftok, const float* __restrict__ tgf,
                            const float* __restrict__ fglob,
                            const float* __restrict__ c1w, const float* __restrict__ c1b,
                            const float* __restrict__ c2w, const float* __restrict__ c2b,
                            float* __restrict__ out) {
    int b = blockIdx.x, tid = threadIdx.x;  // 384
    __shared__ float w3[3];
    __shared__ float fa[D_];
    __shared__ float red[768];
    if (tid == 0) {
        float s3[3] = {stok[b], sphr[b], sglob[b]};
        float h16[16];
        for (int j = 0; j < 16; j++) {
            float v = f1b[j];
            for (int i = 0; i < 3; i++) v += s3[i] * f1w[i * 16 + j];
            h16[j] = 0.5f * v * (1.0f + erff(v * 0.70710678118654752f));  // exact gelu
        }
        for (int c = 0; c < 3; c++) {
            float v = f2b[c];
            for (int j = 0; j < 16; j++) v += h16[j] * f2w[j * 3 + c];
            w3[c] = 1.0f / (1.0f + expf(-v));
        }
    }
    __syncthreads();
    for (int d = tid; d < D_; d += 384)
        fa[d] = w3[0] * ftok[b * D_ + d] + w3[1] * tgf[b * D_ + d] + w3[2] * fglob[b * D_ + d];
    __syncthreads();
    float hj = c1b[tid];
    for (int d = 0; d < D_; d++) hj += fa[d] * c1w[(size_t)d * 384 + tid];
    hj = fmaxf(hj, 0.f);
    red[tid] = hj * c2w[tid * 2];
    red[384 + tid] = hj * c2w[tid * 2 + 1];
    __syncthreads();
    if (tid < 128) {  // collapse 384 -> 128
        red[tid] += red[tid + 128] + red[tid + 256];
        red[384 + tid] += red[384 + tid + 128] + red[384 + tid + 256];
    }
    __syncthreads();
    for (int o = 64; o; o >>= 1) {
        if (tid < o) { red[tid] += red[tid + o]; red[384 + tid] += red[384 + tid + o]; }
        __syncthreads();
    }
    if (tid == 0) {
        out[b * 2 + 0] = red[0] + c2b[0];
        out[b * 2 + 1] = red[384] + c2b[1];
    }
}

// ---------------- host launcher ----------------
extern "C" void kernel_launch(void* const* d_in, const int* in_sizes, int n_in,
                              void* d_out, int out_size) {
    const float* text       = (const float*)d_in[0];
    const float* image      = (const float*)d_in[1];
    const float* clip_text  = (const float*)d_in[2];
    const float* clip_image = (const float*)d_in[3];
    const float* logit_sc   = (const float*)d_in[4];
    const float* wq = (const float*)d_in[5];  const float* bq = (const float*)d_in[6];
    const float* wk = (const float*)d_in[7];  const float* bk = (const float*)d_in[8];
    const float* wv = (const float*)d_in[9];  const float* bv = (const float*)d_in[10];
    const float* wo = (const float*)d_in[11]; const float* bo = (const float*)d_in[12];
    const float* Wt = (const float*)d_in[13]; const float* at = (const float*)d_in[14];
    const float* Wi = (const float*)d_in[15]; const float* ai = (const float*)d_in[16];
    const float* Wp = (const float*)d_in[17]; const float* bp = (const float*)d_in[18];
    const float* f1w = (const float*)d_in[19]; const float* f1b = (const float*)d_in[20];
    const float* f2w = (const float*)d_in[21]; const float* f2b = (const float*)d_in[22];
    const float* c1w = (const float*)d_in[23]; const float* c1b = (const float*)d_in[24];
    const float* c2w = (const float*)d_in[25]; const float* c2b = (const float*)d_in[26];
    const int* text_adj  = (const int*)d_in[27];
    const int* image_adj = (const int*)d_in[28];
    float* out = (float*)d_out;

    float *p_q, *p_k, *p_v, *p_attn, *p_upd, *p_wht, *p_whi;
    float *p_tgf, *p_igf, *p_ftok, *p_fglob, *p_stok, *p_sphr, *p_sglob;
    cudaGetSymbolAddress((void**)&p_q, g_q);
    cudaGetSymbolAddress((void**)&p_k, g_k);
    cudaGetSymbolAddress((void**)&p_v, g_v);
    cudaGetSymbolAddress((void**)&p_attn, g_attn);
    cudaGetSymbolAddress((void**)&p_upd, g_upd);
    cudaGetSymbolAddress((void**)&p_wht, g_wht);
    cudaGetSymbolAddress((void**)&p_whi, g_whi);
    cudaGetSymbolAddress((void**)&p_tgf, g_tgf);
    cudaGetSymbolAddress((void**)&p_igf, g_igf);
    cudaGetSymbolAddress((void**)&p_ftok, g_ftok);
    cudaGetSymbolAddress((void**)&p_fglob, g_fglob);
    cudaGetSymbolAddress((void**)&p_stok, g_stok);
    cudaGetSymbolAddress((void**)&p_sphr, g_sphr);
    cudaGetSymbolAddress((void**)&p_sglob, g_sglob);

    // smem sizes
    const int gatI_smem = (P_ * 66 + 49 * P_ + 2 * P_ + 49 + 128) * 4;   // ~92.4 KB
    const int gatT_smem = (T_ * 66 + 64 * T_ + 2 * T_ + 64 + 128) * 4;   // ~34.6 KB
    cudaFuncSetAttribute(attn_kernel, cudaFuncAttributeMaxDynamicSharedMemorySize, ATTN_SMEM);
    cudaFuncSetAttribute(gat_fused_kernel<P_, 49>, cudaFuncAttributeMaxDynamicSharedMemorySize, gatI_smem);
    cudaFuncSetAttribute(gat_fused_kernel<T_, 64>, cudaFuncAttributeMaxDynamicSharedMemorySize, gatT_smem);

    // zero the accumulators (tgf, igf, stok)
    zero3_kernel<<<(B_ * D_ + 255) / 256, 256>>>(p_tgf, p_igf, p_stok, B_ * D_, B_);

    // projections
    sgemm_kernel<<<dim3(6, 16), 256>>>(text, wq, bq, p_q, B_ * T_, D_, D_);
    sgemm_kernel<<<dim3(6, 49), 256>>>(image, wk, bk, p_k, B_ * P_, D_, D_);
    sgemm_kernel<<<dim3(6, 49), 256>>>(image, wv, bv, p_v, B_ * P_, D_, D_);
    sgemm_kernel<<<dim3(6, 16), 256>>>(text, Wt, nullptr, p_wht, B_ * T_, D_, D_);
    sgemm_kernel<<<dim3(6, 49), 256>>>(image, Wi, nullptr, p_whi, B_ * P_, D_, D_);

    // cross attention + output projection
    attn_kernel<<<dim3(H_, B_), 256, ATTN_SMEM>>>(p_q, p_k, p_v, p_attn);
    sgemm_kernel<<<dim3(6, 16), 256>>>(p_attn, wo, bo, p_upd, B_ * T_, D_, D_);

    // fused GATs (src/dst + softmax + aggregation + ELU + mean)
    gat_fused_kernel<T_, 64><<<dim3(1, H_, B_), 256, gatT_smem>>>(p_wht, at, text_adj, T_ * T_, p_tgf);
    gat_fused_kernel<P_, 49><<<dim3(4, H_, B_), 256, gatI_smem>>>(p_whi, ai, image_adj, 0, p_igf);

    // scalar scores + global feature
    ftok_kernel<<<(B_ * D_) / 256, 256>>>(p_upd, p_ftok);
    stok_kernel<<<(B_ * T_ * 32) / 256, 256>>>(p_upd, image, p_stok);
    fglobal_kernel<<<dim3(6, B_), 128>>>(clip_text, Wp, bp, p_fglob);
    cos_kernel<<<B_, 256>>>(p_tgf, p_igf, clip_text, clip_image, logit_sc, p_sphr, p_sglob);

    // fusion head
    head_kernel<<<B_, 384>>>(p_stok, p_sphr, p_sglob, f1w, f1b, f2w, f2b,
                             p_ftok, p_tgf, p_fglob, c1w, c1b, c2w, c2b, out);
}

// round 11
// speedup vs baseline: 2.1565x; 1.2116x over previous
#include <cuda_runtime.h>
#include <cuda_bf16.h>
#include <mma.h>
#include <math.h>
#include <stdint.h>

using namespace nvcuda;

// Problem constants
#define B_  32
#define T_  64
#define P_  196
#define D_  768
#define H_  12
#define HD_ 64

// ---------------- scratch (static device globals; no allocations) ----------------
__device__ float g_q   [B_*T_*D_];
__device__ float g_k   [B_*P_*D_];
__device__ float g_v   [B_*P_*D_];
__device__ float g_attn[B_*T_*D_];
__device__ float g_upd [B_*T_*D_];
__device__ float g_wht [B_*T_*D_];
__device__ float g_whi [B_*P_*D_];
__device__ float g_tgf[B_*D_], g_igf[B_*D_], g_ftok[B_*D_], g_fglob[B_*D_];
__device__ float g_stok[B_], g_sphr[B_], g_sglob[B_];

// fp32 -> (hi bf16x2, lo bf16x2) split for a float4 (elements in memory order)
__device__ __forceinline__ void cvt_split4(float4 v, uint2& hi, uint2& lo) {
    uint32_t h0, h1;
    asm("cvt.rn.bf16x2.f32 %0, %1, %2;" : "=r"(h0) : "f"(v.y), "f"(v.x));
    asm("cvt.rn.bf16x2.f32 %0, %1, %2;" : "=r"(h1) : "f"(v.w), "f"(v.z));
    float r0 = v.x - __uint_as_float(h0 << 16);
    float r1 = v.y - __uint_as_float(h0 & 0xFFFF0000u);
    float r2 = v.z - __uint_as_float(h1 << 16);
    float r3 = v.w - __uint_as_float(h1 & 0xFFFF0000u);
    uint32_t l0, l1;
    asm("cvt.rn.bf16x2.f32 %0, %1, %2;" : "=r"(l0) : "f"(r1), "f"(r0));
    asm("cvt.rn.bf16x2.f32 %0, %1, %2;" : "=r"(l1) : "f"(r3), "f"(r2));
    hi = make_uint2(h0, h1);
    lo = make_uint2(l0, l1);
}

// ---------------- utility ----------------
__global__ void zero3_kernel(float* a, float* b, float* c, int n, int nc) {
    int i = blockIdx.x * blockDim.x + threadIdx.x;
    if (i < n) { a[i] = 0.f; b[i] = 0.f; }
    if (i < nc) c[i] = 0.f;
}

// ---------------- WMMA bf16-split GEMM: C[M,768] = A[M,768] @ W[768,768] (+bias) --
// C ~= Ah*Wh + Ah*Wl + Al*Wh, fp32 accumulation. CTA tile 128x128, 8 warps,
// warp tile 64x32 (4x2 fragments 16x16x16), K-chunks of 32, double-buffered smem.
#define GLDA 48
#define GLDB 144
#define GASZ (128 * GLDA)          // bf16 elems per A buffer
#define GBSZ (32 * GLDB)           // bf16 elems per B buffer
#define GSTAGE (2 * GASZ + 2 * GBSZ)
#define GEMM_SMEM (2 * GSTAGE * 2) // bytes: 86016

__global__ __launch_bounds__(256, 1)
void wmma_gemm_kernel(const float* __restrict__ A, const float* __restrict__ W,
                      const float* __restrict__ bias, float* __restrict__ C, int M) {
    constexpr int K = 768, N = 768;
    extern __shared__ __align__(1024) uint8_t dsm[];
    __nv_bfloat16* s = (__nv_bfloat16*)dsm;
    int tid = threadIdx.x, wid = tid >> 5;
    int warp_m = wid & 1, warp_n = wid >> 1;   // 2 x 4 warp grid
    int m0 = blockIdx.y * 128, n0 = blockIdx.x * 128;

    wmma::fragment<wmma::accumulator, 16, 16, 16, float> acc[4][2];
#pragma unroll
    for (int i = 0; i < 4; i++)
#pragma unroll
        for (int j = 0; j < 2; j++) wmma::fill_fragment(acc[i][j], 0.f);

    float4 ar[4], br[4];
    // prefetch chunk 0
#pragma unroll
    for (int i = 0; i < 4; i++) {
        int q = i * 256 + tid;
        ar[i] = *(const float4*)(A + (size_t)(m0 + (q >> 3)) * K + ((q & 7) << 2));
        br[i] = *(const float4*)(W + (size_t)(q >> 5) * N + n0 + ((q & 31) << 2));
    }
    // store stage 0
    {
        __nv_bfloat16 *Ah = s, *Al = Ah + GASZ, *Bh = Al + GASZ, *Bl = Bh + GBSZ;
#pragma unroll
        for (int i = 0; i < 4; i++) {
            int q = i * 256 + tid;
            uint2 hi, lo;
            cvt_split4(ar[i], hi, lo);
            int off = (q >> 3) * GLDA + ((q & 7) << 2);
            *(uint2*)(Ah + off) = hi;
            *(uint2*)(Al + off) = lo;
            cvt_split4(br[i], hi, lo);
            off = (q >> 5) * GLDB + ((q & 31) << 2);
            *(uint2*)(Bh + off) = hi;
            *(uint2*)(Bl + off) = lo;
        }
    }
    __syncthreads();

    for (int c = 0; c < 24; c++) {
        if (c + 1 < 24) {
            int kc = (c + 1) * 32;
#pragma unroll
            for (int i = 0; i < 4; i++) {
                int q = i * 256 + tid;
                ar[i] = *(const float4*)(A + (size_t)(m0 + (q >> 3)) * K + kc + ((q & 7) << 2));
                br[i] = *(const float4*)(W + (size_t)(kc + (q >> 5)) * N + n0 + ((q & 31) << 2));
            }
        }
        __nv_bfloat16* Ah = s + (c & 1) * GSTAGE;
        __nv_bfloat16* Al = Ah + GASZ;
        __nv_bfloat16* Bh = Al + GASZ;
        __nv_bfloat16* Bl = Bh + GBSZ;
#pragma unroll
        for (int ks = 0; ks < 32; ks += 16) {
            wmma::fragment<wmma::matrix_a, 16, 16, 16, __nv_bfloat16, wmma::row_major> fah[4], fal[4];
            wmma::fragment<wmma::matrix_b, 16, 16, 16, __nv_bfloat16, wmma::row_major> fbh[2], fbl[2];
#pragma unroll
            for (int i = 0; i < 4; i++) {
                wmma::load_matrix_sync(fah[i], Ah + (warp_m * 64 + i * 16) * GLDA + ks, GLDA);
                wmma::load_matrix_sync(fal[i], Al + (warp_m * 64 + i * 16) * GLDA + ks, GLDA);
            }
#pragma unroll
            for (int j = 0; j < 2; j++) {
                wmma::load_matrix_sync(fbh[j], Bh + ks * GLDB + warp_n * 32 + j * 16, GLDB);
                wmma::load_matrix_sync(fbl[j], Bl + ks * GLDB + warp_n * 32 + j * 16, GLDB);
            }
#pragma unroll
            for (int i = 0; i < 4; i++)
#pragma unroll
                for (int j = 0; j < 2; j++) {
                    wmma::mma_sync(acc[i][j], fah[i], fbh[j], acc[i][j]);
                    wmma::mma_sync(acc[i][j], fah[i], fbl[j], acc[i][j]);
                    wmma::mma_sync(acc[i][j], fal[i], fbh[j], acc[i][j]);
                }
        }
        if (c + 1 < 24) {
            __nv_bfloat16* nAh = s + ((c + 1) & 1) * GSTAGE;
            __nv_bfloat16* nAl = nAh + GASZ;
            __nv_bfloat16* nBh = nAl + GASZ;
            __nv_bfloat16* nBl = nBh + GBSZ;
#pragma unroll
            for (int i = 0; i < 4; i++) {
                int q = i * 256 + tid;
                uint2 hi, lo;
                cvt_split4(ar[i], hi, lo);
                int off = (q >> 3) * GLDA + ((q & 7) << 2);
                *(uint2*)(nAh + off) = hi;
                *(uint2*)(nAl + off) = lo;
                cvt_split4(br[i], hi, lo);
                off = (q >> 5) * GLDB + ((q & 31) << 2);
                *(uint2*)(nBh + off) = hi;
                *(uint2*)(nBl + off) = lo;
            }
        }
        __syncthreads();
    }

    // epilogue: accum -> smem -> coalesced gmem + bias
    float* ep = (float*)dsm;
#pragma unroll
    for (int i = 0; i < 4; i++)
#pragma unroll
        for (int j = 0; j < 2; j++)
            wmma::store_matrix_sync(ep + (warp_m * 64 + i * 16) * 136 + warp_n * 32 + j * 16,
                                    acc[i][j], 136, wmma::mem_row_major);
    __syncthreads();
    int cq = (tid & 31) << 2;
    float4 bb = make_float4(0.f, 0.f, 0.f, 0.f);
    if (bias) bb = *(const float4*)(bias + n0 + cq);
#pragma unroll
    for (int i = 0; i < 16; i++) {
        int r = i * 8 + (tid >> 5);
        float4 o = *(float4*)(ep + r * 136 + cq);
        o.x += bb.x; o.y += bb.y; o.z += bb.z; o.w += bb.w;
        *(float4*)(C + (size_t)(m0 + r) * N + n0 + cq) = o;
    }
}

// ---------------- cross attention: per (b,h); warp-per-2-timesteps ----------------
#define KV_STRIDE 66
#define ATTN_SMEM ((2 * P_ * KV_STRIDE + 8 * 132) * 4)
__global__ void attn_kernel(const float* __restrict__ q, const float* __restrict__ k,
                            const float* __restrict__ v, float* __restrict__ out) {
    int h = blockIdx.x, b = blockIdx.y;
    extern __shared__ float sm[];
    float* Ks = sm;                       // [P_][66]
    float* Vs = Ks + P_ * KV_STRIDE;      // [P_][66]
    float* qs = Vs + P_ * KV_STRIDE;      // [8 warps][2*66]
    int tid = threadIdx.x, lane = tid & 31, w = tid >> 5;

    for (int idx = tid; idx < P_ * 64; idx += 256) {
        int p = idx >> 6, d = idx & 63;
        size_t g = (size_t)(b * P_ + p) * D_ + h * 64 + d;
        Ks[p * KV_STRIDE + d] = k[g];
        Vs[p * KV_STRIDE + d] = v[g];
    }
    __syncthreads();

    float* myq = qs + w * 132;
    int ro[7];
#pragma unroll
    for (int r = 0; r < 7; r++) {
        int p = lane + 32 * r;
        ro[r] = (p < P_ ? p : P_ - 1) * KV_STRIDE;
    }

    for (int s = 0; s < 4; s++) {
        int t0 = w * 8 + s * 2;
        __syncwarp();
        myq[lane]       = q[(size_t)(b * T_ + t0) * D_ + h * 64 + lane];
        myq[lane + 32]  = q[(size_t)(b * T_ + t0) * D_ + h * 64 + lane + 32];
        myq[66 + lane]      = q[(size_t)(b * T_ + t0 + 1) * D_ + h * 64 + lane];
        myq[66 + lane + 32] = q[(size_t)(b * T_ + t0 + 1) * D_ + h * 64 + lane + 32];
        __syncwarp();

        float acc[2][7];
#pragma unroll
        for (int r = 0; r < 7; r++) { acc[0][r] = 0.f; acc[1][r] = 0.f; }
        for (int d = 0; d < 64; d++) {
            float q0 = myq[d], q1 = myq[66 + d];
#pragma unroll
            for (int r = 0; r < 7; r++) {
                float kv = Ks[ro[r] + d];
                acc[0][r] += q0 * kv;
                acc[1][r] += q1 * kv;
            }
        }

        float rZ[2];
#pragma unroll
        for (int tt = 0; tt < 2; tt++) {
            float m = -1e30f;
#pragma unroll
            for (int r = 0; r < 7; r++)
                if (lane + 32 * r < P_) m = fmaxf(m, acc[tt][r] * 0.125f);
#pragma unroll
            for (int o = 16; o; o >>= 1) m = fmaxf(m, __shfl_xor_sync(0xffffffffu, m, o));
            float Z = 0.f;
#pragma unroll
            for (int r = 0; r < 7; r++) {
                float wv = (lane + 32 * r < P_) ? expf(acc[tt][r] * 0.125f - m) : 0.f;
                acc[tt][r] = wv;
                Z += wv;
            }
#pragma unroll
            for (int o = 16; o; o >>= 1) Z += __shfl_xor_sync(0xffffffffu, Z, o);
            rZ[tt] = 1.f / Z;
        }

        float ov00 = 0.f, ov01 = 0.f, ov10 = 0.f, ov11 = 0.f;
#pragma unroll
        for (int r = 0; r < 6; r++) {
            int pl = 32 * r;
            for (int sl = 0; sl < 32; sl++) {
                float w0 = __shfl_sync(0xffffffffu, acc[0][r], sl);
                float w1 = __shfl_sync(0xffffffffu, acc[1][r], sl);
                float v0 = Vs[(pl + sl) * KV_STRIDE + lane];
                float v1 = Vs[(pl + sl) * KV_STRIDE + lane + 32];
                ov00 += w0 * v0; ov01 += w0 * v1;
                ov10 += w1 * v0; ov11 += w1 * v1;
            }
        }
        for (int sl = 0; sl < P_ - 192; sl++) {
            float w0 = __shfl_sync(0xffffffffu, acc[0][6], sl);
            float w1 = __shfl_sync(0xffffffffu, acc[1][6], sl);
            float v0 = Vs[(192 + sl) * KV_STRIDE + lane];
            float v1 = Vs[(192 + sl) * KV_STRIDE + lane + 32];
            ov00 += w0 * v0; ov01 += w0 * v1;
            ov10 += w1 * v0; ov11 += w1 * v1;
        }
        size_t o0 = (size_t)(b * T_ + t0) * D_ + h * 64 + lane;
        size_t o1 = (size_t)(b * T_ + t0 + 1) * D_ + h * 64 + lane;
        out[o0]      = ov00 * rZ[0];
        out[o0 + 32] = ov01 * rZ[0];
        out[o1]      = ov10 * rZ[1];
        out[o1 + 32] = ov11 * rZ[1];
    }
}

// ---------------- fully fused GAT: src/dst + masked softmax + agg + ELU + mean ----
template <int N, int ITILE>
__global__ void gat_fused_kernel(const float* __restrict__ Wh,
                                 const float* __restrict__ avec,
                                 const int* __restrict__ adj, int adjBatchStride,
                                 float* __restrict__ outmean) {
    constexpr int NPAD = 66;
    constexpr int NR = (N + 31) / 32;
    constexpr int MI = (ITILE + 7) / 8;
    int tile = blockIdx.x, h = blockIdx.y, b = blockIdx.z;
    int i0 = tile * ITILE;
    extern __shared__ float sm[];
    float* Whs  = sm;
    float* Ws   = Whs + N * NPAD;
    float* srcs = Ws + ITILE * N;
    float* dsts = srcs + N;
    float* zinv = dsts + N;
    float* as   = zinv + ITILE;
    int tid = threadIdx.x, lane = tid & 31, wid = tid >> 5;

    if (tid < 128) as[tid] = avec[tid];
    for (int idx = tid; idx < N * 64; idx += 256) {
        int j = idx >> 6, f = idx & 63;
        Whs[j * NPAD + f] = Wh[(size_t)(b * N + j) * D_ + h * 64 + f];
    }
    __syncthreads();

    for (int j = tid; j < N; j += 256) {
        float s = 0.f, d = 0.f;
#pragma unroll 8
        for (int f = 0; f < 64; f++) {
            float wv = Whs[j * NPAD + f];
            s += wv * as[f];
            d += wv * as[64 + f];
        }
        srcs[j] = s;
        dsts[j] = d;
    }
    __syncthreads();

    for (int iloc = wid; iloc < ITILE; iloc += 8) {
        int i = i0 + iloc;
        float si = srcs[i];
        float ev[NR];
        float m = -1e30f;
#pragma unroll
        for (int r = 0; r < NR; r++) {
            int j = lane + 32 * r;
            float e = -1e30f;
            if (j < N) {
                int a = adj[(size_t)b * adjBatchStride + (size_t)i * N + j];
                if (a > 0) {
                    float x = si + dsts[j];
                    e = x > 0.f ? x : 0.2f * x;
                }
            }
            ev[r] = e;
            m = fmaxf(m, e);
        }
#pragma unroll
        for (int o = 16; o; o >>= 1) m = fmaxf(m, __shfl_xor_sync(0xffffffffu, m, o));
        float Z = 0.f;
#pragma unroll
        for (int r = 0; r < NR; r++) {
            int j = lane + 32 * r;
            float wv = (ev[r] > -1e29f) ? expf(ev[r] - m) : 0.f;
            if (j < N) Ws[iloc * N + j] = wv;
            Z += wv;
        }
#pragma unroll
        for (int o = 16; o; o >>= 1) Z += __shfl_xor_sync(0xffffffffu, Z, o);
        if (lane == 0) zinv[iloc] = 1.f / Z;
    }
    __syncthreads();

    int f2 = lane * 2;
    float acc0[MI], acc1[MI];
#pragma unroll
    for (int m = 0; m < MI; m++) { acc0[m] = 0.f; acc1[m] = 0.f; }
    for (int j = 0; j < N; j++) {
        float2 wh = *(const float2*)&Whs[j * NPAD + f2];
#pragma unroll
        for (int m = 0; m < MI; m++) {
            int iloc = wid + 8 * m;
            float wv = (iloc < ITILE) ? Ws[iloc * N + j] : 0.f;
            acc0[m] += wv * wh.x;
            acc1[m] += wv * wh.y;
        }
    }
    float s0 = 0.f, s1 = 0.f;
#pragma unroll
    for (int m = 0; m < MI; m++) {
        int iloc = wid + 8 * m;
        if (iloc < ITILE) {
            float z = zinv[iloc];
            float v0 = acc0[m] * z, v1 = acc1[m] * z;
            v0 = v0 > 0.f ? v0 : expm1f(v0);
            v1 = v1 > 0.f ? v1 : expm1f(v1);
            s0 += v0;
            s1 += v1;
        }
    }
    atomicAdd(&outmean[b * D_ + h * 64 + f2],     s0 * (1.0f / N));
    atomicAdd(&outmean[b * D_ + h * 64 + f2 + 1], s1 * (1.0f / N));
}

// ---------------- f_token = mean_t upd ----------------
__global__ void ftok_kernel(const float* __restrict__ upd, float* __restrict__ ftok) {
    int idx = blockIdx.x * 256 + threadIdx.x;
    int b = idx / D_, d = idx - b * D_;
    float s = 0.f;
    for (int t = 0; t < T_; t++) s += upd[(size_t)(b * T_ + t) * D_ + d];
    ftok[idx] = s * (1.0f / T_);
}

// ---------------- s_token: warp per (b,t) diag dot ----------------
__global__ void stok_kernel(const float* __restrict__ upd, const float* __restrict__ img,
                            float* __restrict__ stok) {
    int gw = (blockIdx.x * 256 + threadIdx.x) >> 5;
    int lane = threadIdx.x & 31;
    int b = gw >> 6, t = gw & 63;
    float a = 0.f;
    for (int d = lane; d < D_; d += 32)
        a += upd[(size_t)(b * T_ + t) * D_ + d] * img[(size_t)(b * P_ + t) * D_ + d];
#pragma unroll
    for (int o = 16; o; o >>= 1) a += __shfl_xor_sync(0xffffffffu, a, o);
    if (lane == 0) atomicAdd(&stok[b], a * (1.0f / T_));
}

// ---------------- f_global = clip_text @ Wp + bp ----------------
__global__ void fglobal_kernel(const float* __restrict__ ct, const float* __restrict__ Wp,
                               const float* __restrict__ bp, float* __restrict__ out) {
    int b = blockIdx.y;
    int n = blockIdx.x * 128 + threadIdx.x;
    float acc = bp[n];
    for (int k = 0; k < 512; k++) acc += ct[b * 512 + k] * Wp[(size_t)k * D_ + n];
    out[b * D_ + n] = acc;
}

// ---------------- cosine scores ----------------
__global__ void cos_kernel(const float* __restrict__ tgf, const float* __restrict__ igf,
                           const float* __restrict__ ct, const float* __restrict__ ci,
                           const float* __restrict__ ls,
                           float* __restrict__ sphr, float* __restrict__ sglob) {
    int b = blockIdx.x, tid = threadIdx.x;
    __shared__ float r0[256], r1[256], r2[256];
    float d0 = 0.f, d1 = 0.f, d2 = 0.f;
    for (int d = tid; d < D_; d += 256) {
        float x = tgf[b * D_ + d], y = igf[b * D_ + d];
        d0 += x * y; d1 += x * x; d2 += y * y;
    }
    r0[tid] = d0; r1[tid] = d1; r2[tid] = d2;
    __syncthreads();
    for (int o = 128; o; o >>= 1) {
        if (tid < o) { r0[tid] += r0[tid + o]; r1[tid] += r1[tid + o]; r2[tid] += r2[tid + o]; }
        __syncthreads();
    }
    if (tid == 0) {
        float nx = fmaxf(sqrtf(r1[0]), 1e-8f), ny = fmaxf(sqrtf(r2[0]), 1e-8f);
        sphr[b] = r0[0] / (nx * ny);
    }
    __syncthreads();
    d0 = d1 = d2 = 0.f;
    for (int d = tid; d < 512; d += 256) {
        float x = ct[b * 512 + d], y = ci[b * 512 + d];
        d0 += x * y; d1 += x * x; d2 += y * y;
    }
    r0[tid] = d0; r1[tid] = d1; r2[tid] = d2;
    __syncthreads();
    for (int o = 128; o; o >>= 1) {
        if (tid < o) { r0[tid] += r0[tid + o]; r1[tid] += r1[tid + o]; r2[tid] += r2[tid + o]; }
        __syncthreads();
    }
    if (tid == 0) {
        float nx = fmaxf(sqrtf(r1[0]), 1e-8f), ny = fmaxf(sqrtf(r2[0]), 1e-8f);
        sglob[b] = expf(*ls) * r0[0] / (nx * ny);
    }
}

// ---------------- fusion head -> logits ----------------
__global__ void head_kernel(const float* __restrict__ stok, const float* __restrict__ sphr,
                            const float* __restrict__ sglob,
                            const float* __restrict__ f1w, const float* __restrict__ f1b,
                            const float* __restrict__ f2w, const float* __restrict__ f2b,
                            const float* __restrict__ ftok, const float* __restrict__ tgf,
                            const float* __restrict__ fglob,
                            const float* __restrict__ c1w, const float* __restrict__ c1b,
                            const float* __restrict__ c2w, const float* __restrict__ c2b,
                            float* __restrict__ out) {
    int b = blockIdx.x, tid = threadIdx.x;  // 384
    __shared__ float w3[3];
    __shared__ float fa[D_];
    __shared__ float red[768];
    if (tid == 0) {
        float s3[3] = {stok[b], sphr[b], sglob[b]};
        float h16[16];
        for (int j = 0; j < 16; j++) {
            float v = f1b[j];
            for (int i = 0; i < 3; i++) v += s3[i] * f1w[i * 16 + j];
            h16[j] = 0.5f * v * (1.0f + erff(v * 0.70710678118654752f));
        }
        for (int c = 0; c < 3; c++) {
            float v = f2b[c];
            for (int j = 0; j < 16; j++) v += h16[j] * f2w[j * 3 + c];
            w3[c] = 1.0f / (1.0f + expf(-v));
        }
    }
    __syncthreads();
    for (int d = tid; d < D_; d += 384)
        fa[d] = w3[0] * ftok[b * D_ + d] + w3[1] * tgf[b * D_ + d] + w3[2] * fglob[b * D_ + d];
    __syncthreads();
    float hj = c1b[tid];
    for (int d = 0; d < D_; d++) hj += fa[d] * c1w[(size_t)d * 384 + tid];
    hj = fmaxf(hj, 0.f);
    red[tid] = hj * c2w[tid * 2];
    red[384 + tid] = hj * c2w[tid * 2 + 1];
    __syncthreads();
    if (tid < 128) {
        red[tid] += red[tid + 128] + red[tid + 256];
        red[384 + tid] += red[384 + tid + 128] + red[384 + tid + 256];
    }
    __syncthreads();
    for (int o = 64; o; o >>= 1) {
        if (tid < o) { red[tid] += red[tid + o]; red[384 + tid] += red[384 + tid + o]; }
        __syncthreads();
    }
    if (tid == 0) {
        out[b * 2 + 0] = red[0] + c2b[0];
        out[b * 2 + 1] = red[384] + c2b[1];
    }
}

// ---------------- host launcher ----------------
extern "C" void kernel_launch(void* const* d_in, const int* in_sizes, int n_in,
                              void* d_out, int out_size) {
    const float* text       = (const float*)d_in[0];
    const float* image      = (const float*)d_in[1];
    const float* clip_text  = (const float*)d_in[2];
    const float* clip_image = (const float*)d_in[3];
    const float* logit_sc   = (const float*)d_in[4];
    const float* wq = (const float*)d_in[5];  const float* bq = (const float*)d_in[6];
    const float* wk = (const float*)d_in[7];  const float* bk = (const float*)d_in[8];
    const float* wv = (const float*)d_in[9];  const float* bv = (const float*)d_in[10];
    const float* wo = (const float*)d_in[11]; const float* bo = (const float*)d_in[12];
    const float* Wt = (const float*)d_in[13]; const float* at = (const float*)d_in[14];
    const float* Wi = (const float*)d_in[15]; const float* ai = (const float*)d_in[16];
    const float* Wp = (const float*)d_in[17]; const float* bp = (const float*)d_in[18];
    const float* f1w = (const float*)d_in[19]; const float* f1b = (const float*)d_in[20];
    const float* f2w = (const float*)d_in[21]; const float* f2b = (const float*)d_in[22];
    const float* c1w = (const float*)d_in[23]; const float* c1b = (const float*)d_in[24];
    const float* c2w = (const float*)d_in[25]; const float* c2b = (const float*)d_in[26];
    const int* text_adj  = (const int*)d_in[27];
    const int* image_adj = (const int*)d_in[28];
    float* out = (float*)d_out;

    float *p_q, *p_k, *p_v, *p_attn, *p_upd, *p_wht, *p_whi;
    float *p_tgf, *p_igf, *p_ftok, *p_fglob, *p_stok, *p_sphr, *p_sglob;
    cudaGetSymbolAddress((void**)&p_q, g_q);
    cudaGetSymbolAddress((void**)&p_k, g_k);
    cudaGetSymbolAddress((void**)&p_v, g_v);
    cudaGetSymbolAddress((void**)&p_attn, g_attn);
    cudaGetSymbolAddress((void**)&p_upd, g_upd);
    cudaGetSymbolAddress((void**)&p_wht, g_wht);
    cudaGetSymbolAddress((void**)&p_whi, g_whi);
    cudaGetSymbolAddress((void**)&p_tgf, g_tgf);
    cudaGetSymbolAddress((void**)&p_igf, g_igf);
    cudaGetSymbolAddress((void**)&p_ftok, g_ftok);
    cudaGetSymbolAddress((void**)&p_fglob, g_fglob);
    cudaGetSymbolAddress((void**)&p_stok, g_stok);
    cudaGetSymbolAddress((void**)&p_sphr, g_sphr);
    cudaGetSymbolAddress((void**)&p_sglob, g_sglob);

    const int gatI_smem = (P_ * 66 + 49 * P_ + 2 * P_ + 49 + 128) * 4;
    const int gatT_smem = (T_ * 66 + 64 * T_ + 2 * T_ + 64 + 128) * 4;
    cudaFuncSetAttribute(wmma_gemm_kernel, cudaFuncAttributeMaxDynamicSharedMemorySize, GEMM_SMEM);
    cudaFuncSetAttribute(attn_kernel, cudaFuncAttributeMaxDynamicSharedMemorySize, ATTN_SMEM);
    cudaFuncSetAttribute(gat_fused_kernel<P_, 49>, cudaFuncAttributeMaxDynamicSharedMemorySize, gatI_smem);
    cudaFuncSetAttribute(gat_fused_kernel<T_, 64>, cudaFuncAttributeMaxDynamicSharedMemorySize, gatT_smem);

    // zero the accumulators (tgf, igf, stok)
    zero3_kernel<<<(B_ * D_ + 255) / 256, 256>>>(p_tgf, p_igf, p_stok, B_ * D_, B_);

    // projections (tensor-core bf16-split GEMMs via WMMA/HMMA)
    wmma_gemm_kernel<<<dim3(6, 16), 256, GEMM_SMEM>>>(text,  wq, bq, p_q,   B_ * T_);
    wmma_gemm_kernel<<<dim3(6, 49), 256, GEMM_SMEM>>>(image, wk, bk, p_k,   B_ * P_);
    wmma_gemm_kernel<<<dim3(6, 49), 256, GEMM_SMEM>>>(image, wv, bv, p_v,   B_ * P_);
    wmma_gemm_kernel<<<dim3(6, 16), 256, GEMM_SMEM>>>(text,  Wt, nullptr, p_wht, B_ * T_);
    wmma_gemm_kernel<<<dim3(6, 49), 256, GEMM_SMEM>>>(image, Wi, nullptr, p_whi, B_ * P_);

    // cross attention + output projection
    attn_kernel<<<dim3(H_, B_), 256, ATTN_SMEM>>>(p_q, p_k, p_v, p_attn);
    wmma_gemm_kernel<<<dim3(6, 16), 256, GEMM_SMEM>>>(p_attn, wo, bo, p_upd, B_ * T_);

    // fused GATs
    gat_fused_kernel<T_, 64><<<dim3(1, H_, B_), 256, gatT_smem>>>(p_wht, at, text_adj, T_ * T_, p_tgf);
    gat_fused_kernel<P_, 49><<<dim3(4, H_, B_), 256, gatI_smem>>>(p_whi, ai, image_adj, 0, p_igf);

    // scalar scores + global feature
    ftok_kernel<<<(B_ * D_) / 256, 256>>>(p_upd, p_ftok);
    stok_kernel<<<(B_ * T_ * 32) / 256, 256>>>(p_upd, image, p_stok);
    fglobal_kernel<<<dim3(6, B_), 128>>>(clip_text, Wp, bp, p_fglob);
    cos_kernel<<<B_, 256>>>(p_tgf, p_igf, clip_text, clip_image, logit_sc, p_sphr, p_sglob);

    // fusion head
    head_kernel<<<B_, 384>>>(p_stok, p_sphr, p_sglob, f1w, f1b, f2w, f2b,
                             p_ftok, p_tgf, p_fglob, c1w, c1b, c2w, c2b, out);
}

// round 12
// speedup vs baseline: 3.0542x; 1.4163x over previous
#include <cuda_runtime.h>
#include <cuda_bf16.h>
#include <mma.h>
#include <math.h>
#include <stdint.h>

using namespace nvcuda;

// Problem constants
#define B_  32
#define T_  64
#define P_  196
#define D_  768
#define H_  12
#define HD_ 64

// ---------------- scratch (static device globals; no allocations) ----------------
__device__ float g_q   [B_*T_*D_];
__device__ float g_k   [B_*P_*D_];
__device__ float g_v   [B_*P_*D_];
__device__ float g_upd [B_*T_*D_];
__device__ float g_wht [B_*T_*D_];
__device__ float g_whi [B_*P_*D_];
__device__ float g_tgf[B_*D_], g_igf[B_*D_], g_ftok[B_*D_], g_fglob[B_*D_];
__device__ float g_stok[B_], g_sphr[B_], g_sglob[B_];
// bf16 hi/lo splits
__device__ __nv_bfloat16 g_th[B_*T_*D_], g_tl[B_*T_*D_];
__device__ __nv_bfloat16 g_ih[B_*P_*D_], g_il[B_*P_*D_];
__device__ __nv_bfloat16 g_ath[B_*T_*D_], g_atl[B_*T_*D_];
__device__ __nv_bfloat16 g_wh6[6][D_*D_], g_wl6[6][D_*D_];

// ---------------- helpers ----------------
__device__ __forceinline__ uint32_t smem_u32(const void* p) {
    uint32_t a;
    asm("{ .reg .u64 t; cvta.to.shared.u64 t, %1; cvt.u32.u64 %0, t; }" : "=r"(a) : "l"(p));
    return a;
}
__device__ __forceinline__ void cp16(uint32_t dst, const void* src) {
    asm volatile("cp.async.cg.shared.global [%0], [%1], 16;\n" :: "r"(dst), "l"(src));
}
// fp32 -> (hi bf16x2, lo bf16x2) split for a float4 (memory order)
__device__ __forceinline__ void cvt_split4(float4 v, uint2& hi, uint2& lo) {
    uint32_t h0, h1;
    asm("cvt.rn.bf16x2.f32 %0, %1, %2;" : "=r"(h0) : "f"(v.y), "f"(v.x));
    asm("cvt.rn.bf16x2.f32 %0, %1, %2;" : "=r"(h1) : "f"(v.w), "f"(v.z));
    float r0 = v.x - __uint_as_float(h0 << 16);
    float r1 = v.y - __uint_as_float(h0 & 0xFFFF0000u);
    float r2 = v.z - __uint_as_float(h1 << 16);
    float r3 = v.w - __uint_as_float(h1 & 0xFFFF0000u);
    uint32_t l0, l1;
    asm("cvt.rn.bf16x2.f32 %0, %1, %2;" : "=r"(l0) : "f"(r1), "f"(r0));
    asm("cvt.rn.bf16x2.f32 %0, %1, %2;" : "=r"(l1) : "f"(r3), "f"(r2));
    hi = make_uint2(h0, h1);
    lo = make_uint2(l0, l1);
}

// ---------------- split kernels ----------------
__global__ void split_kernel(const float* __restrict__ src, __nv_bfloat16* __restrict__ dh,
                             __nv_bfloat16* __restrict__ dl, int n4) {
    int i = blockIdx.x * 256 + threadIdx.x;
    if (i < n4) {
        float4 v = ((const float4*)src)[i];
        uint2 hi, lo;
        cvt_split4(v, hi, lo);
        ((uint2*)dh)[i] = hi;
        ((uint2*)dl)[i] = lo;
    }
}
struct SixPtr { const float* s[6]; __nv_bfloat16* h; __nv_bfloat16* l; };
__global__ void split6_kernel(SixPtr p, int n4) {
    int m = blockIdx.y;
    int i = blockIdx.x * 256 + threadIdx.x;
    if (i < n4) {
        float4 v = ((const float4*)p.s[m])[i];
        uint2 hi, lo;
        cvt_split4(v, hi, lo);
        ((uint2*)(p.h + (size_t)m * D_ * D_))[i] = hi;
        ((uint2*)(p.l + (size_t)m * D_ * D_))[i] = lo;
    }
}

__global__ void zero3_kernel(float* a, float* b, float* c, int n, int nc) {
    int i = blockIdx.x * blockDim.x + threadIdx.x;
    if (i < n) { a[i] = 0.f; b[i] = 0.f; }
    if (i < nc) c[i] = 0.f;
}

// ---------------- bf16-split GEMM (pre-split operands, cp.async 4-stage) ----------
// C[M,768] = A @ W (+bias), C ~= Ah*Wh + Ah*Wl + Al*Wh, fp32 accum.
// CTA 128x128, 8 warps (2x4), warp tile 64x32 (4x2 frags), K-chunks of 32.
#define LDAs 40
#define LDBs 136
#define ASZ (128 * LDAs)               // 5120 bf16
#define BSZ (32 * LDBs)                // 4352 bf16
#define STG (2 * ASZ + 2 * BSZ)        // 18944 bf16 per stage
#define GEMM_SMEM (4 * STG * 2)        // 151552 bytes

__global__ __launch_bounds__(256, 1)
void bf16_gemm_kernel(const __nv_bfloat16* __restrict__ Ah, const __nv_bfloat16* __restrict__ Al,
                      const __nv_bfloat16* __restrict__ Wh, const __nv_bfloat16* __restrict__ Wl,
                      const float* __restrict__ bias, float* __restrict__ C, int M) {
    constexpr int K = 768, N = 768;
    extern __shared__ __align__(1024) uint8_t dsm[];
    int tid = threadIdx.x, wid = tid >> 5;
    int warp_m = wid & 1, warp_n = wid >> 1;
    int m0 = blockIdx.y * 128, n0 = blockIdx.x * 128;
    uint32_t sb = smem_u32(dsm);

    wmma::fragment<wmma::accumulator, 16, 16, 16, float> acc[4][2];
#pragma unroll
    for (int i = 0; i < 4; i++)
#pragma unroll
        for (int j = 0; j < 2; j++) wmma::fill_fragment(acc[i][j], 0.f);

    auto issue = [&](int c) {
        int kc = c * 32;
        uint32_t st = sb + (uint32_t)(c & 3) * (STG * 2);
#pragma unroll
        for (int s = 0; s < 2; s++) {
            const __nv_bfloat16* g = s ? Al : Ah;
            uint32_t d0 = st + s * (ASZ * 2);
#pragma unroll
            for (int i = 0; i < 2; i++) {
                int q = i * 256 + tid;             // 0..511
                int row = q >> 2, kcol = (q & 3) << 3;
                cp16(d0 + (uint32_t)(row * LDAs + kcol) * 2,
                     g + (size_t)(m0 + row) * K + kc + kcol);
            }
        }
#pragma unroll
        for (int s = 0; s < 2; s++) {
            const __nv_bfloat16* g = s ? Wl : Wh;
            uint32_t d0 = st + (2 * ASZ + s * BSZ) * 2;
#pragma unroll
            for (int i = 0; i < 2; i++) {
                int q = i * 256 + tid;             // 0..511
                int row = q >> 4, col = (q & 15) << 3;
                cp16(d0 + (uint32_t)(row * LDBs + col) * 2,
                     g + (size_t)(kc + row) * N + n0 + col);
            }
        }
        asm volatile("cp.async.commit_group;\n" ::);
    };

    issue(0); issue(1); issue(2);

    for (int c = 0; c < 24; c++) {
        if (c < 22)      asm volatile("cp.async.wait_group 2;\n" ::);
        else if (c < 23) asm volatile("cp.async.wait_group 1;\n" ::);
        else             asm volatile("cp.async.wait_group 0;\n" ::);
        __syncthreads();
        const __nv_bfloat16* st = (const __nv_bfloat16*)(dsm + (size_t)(c & 3) * (STG * 2));
        const __nv_bfloat16* Ahs = st;
        const __nv_bfloat16* Als = st + ASZ;
        const __nv_bfloat16* Bhs = st + 2 * ASZ;
        const __nv_bfloat16* Bls = st + 2 * ASZ + BSZ;
#pragma unroll
        for (int ks = 0; ks < 32; ks += 16) {
            wmma::fragment<wmma::matrix_a, 16, 16, 16, __nv_bfloat16, wmma::row_major> fah[4], fal[4];
            wmma::fragment<wmma::matrix_b, 16, 16, 16, __nv_bfloat16, wmma::row_major> fbh[2], fbl[2];
#pragma unroll
            for (int i = 0; i < 4; i++) {
                wmma::load_matrix_sync(fah[i], Ahs + (warp_m * 64 + i * 16) * LDAs + ks, LDAs);
                wmma::load_matrix_sync(fal[i], Als + (warp_m * 64 + i * 16) * LDAs + ks, LDAs);
            }
#pragma unroll
            for (int j = 0; j < 2; j++) {
                wmma::load_matrix_sync(fbh[j], Bhs + ks * LDBs + warp_n * 32 + j * 16, LDBs);
                wmma::load_matrix_sync(fbl[j], Bls + ks * LDBs + warp_n * 32 + j * 16, LDBs);
            }
#pragma unroll
            for (int i = 0; i < 4; i++)
#pragma unroll
                for (int j = 0; j < 2; j++) {
                    wmma::mma_sync(acc[i][j], fah[i], fbh[j], acc[i][j]);
                    wmma::mma_sync(acc[i][j], fah[i], fbl[j], acc[i][j]);
                    wmma::mma_sync(acc[i][j], fal[i], fbh[j], acc[i][j]);
                }
        }
        if (c + 3 < 24) issue(c + 3);
    }
    __syncthreads();

    // epilogue: accum -> smem -> coalesced gmem + bias
    float* ep = (float*)dsm;
#pragma unroll
    for (int i = 0; i < 4; i++)
#pragma unroll
        for (int j = 0; j < 2; j++)
            wmma::store_matrix_sync(ep + (warp_m * 64 + i * 16) * 136 + warp_n * 32 + j * 16,
                                    acc[i][j], 136, wmma::mem_row_major);
    __syncthreads();
    int cq = (tid & 31) << 2;
    float4 bb = make_float4(0.f, 0.f, 0.f, 0.f);
    if (bias) bb = *(const float4*)(bias + n0 + cq);
#pragma unroll
    for (int i = 0; i < 16; i++) {
        int r = i * 8 + (tid >> 5);
        float4 o = *(float4*)(ep + r * 136 + cq);
        o.x += bb.x; o.y += bb.y; o.z += bb.z; o.w += bb.w;
        *(float4*)(C + (size_t)(m0 + r) * N + n0 + cq) = o;
    }
}

// ---------------- cross attention: per (b,h); warp-per-2-timesteps ----------------
// Writes output directly as bf16 hi/lo splits (for the wo GEMM).
#define KV_STRIDE 66
#define ATTN_SMEM ((2 * P_ * KV_STRIDE + 8 * 132) * 4)
__device__ __forceinline__ void store_split(__nv_bfloat16* ph, __nv_bfloat16* pl,
                                            size_t idx, float v) {
    __nv_bfloat16 hb = __float2bfloat16(v);
    float hf = __bfloat162float(hb);
    ph[idx] = hb;
    pl[idx] = __float2bfloat16(v - hf);
}
__global__ void attn_kernel(const float* __restrict__ q, const float* __restrict__ k,
                            const float* __restrict__ v,
                            __nv_bfloat16* __restrict__ outh, __nv_bfloat16* __restrict__ outl) {
    int h = blockIdx.x, b = blockIdx.y;
    extern __shared__ float sm[];
    float* Ks = sm;
    float* Vs = Ks + P_ * KV_STRIDE;
    float* qs = Vs + P_ * KV_STRIDE;
    int tid = threadIdx.x, lane = tid & 31, w = tid >> 5;

    for (int idx = tid; idx < P_ * 64; idx += 256) {
        int p = idx >> 6, d = idx & 63;
        size_t g = (size_t)(b * P_ + p) * D_ + h * 64 + d;
        Ks[p * KV_STRIDE + d] = k[g];
        Vs[p * KV_STRIDE + d] = v[g];
    }
    __syncthreads();

    float* myq = qs + w * 132;
    int ro[7];
#pragma unroll
    for (int r = 0; r < 7; r++) {
        int p = lane + 32 * r;
        ro[r] = (p < P_ ? p : P_ - 1) * KV_STRIDE;
    }

    for (int s = 0; s < 4; s++) {
        int t0 = w * 8 + s * 2;
        __syncwarp();
        myq[lane]       = q[(size_t)(b * T_ + t0) * D_ + h * 64 + lane];
        myq[lane + 32]  = q[(size_t)(b * T_ + t0) * D_ + h * 64 + lane + 32];
        myq[66 + lane]      = q[(size_t)(b * T_ + t0 + 1) * D_ + h * 64 + lane];
        myq[66 + lane + 32] = q[(size_t)(b * T_ + t0 + 1) * D_ + h * 64 + lane + 32];
        __syncwarp();

        float acc[2][7];
#pragma unroll
        for (int r = 0; r < 7; r++) { acc[0][r] = 0.f; acc[1][r] = 0.f; }
        for (int d = 0; d < 64; d++) {
            float q0 = myq[d], q1 = myq[66 + d];
#pragma unroll
            for (int r = 0; r < 7; r++) {
                float kv = Ks[ro[r] + d];
                acc[0][r] += q0 * kv;
                acc[1][r] += q1 * kv;
            }
        }

        float rZ[2];
#pragma unroll
        for (int tt = 0; tt < 2; tt++) {
            float m = -1e30f;
#pragma unroll
            for (int r = 0; r < 7; r++)
                if (lane + 32 * r < P_) m = fmaxf(m, acc[tt][r] * 0.125f);
#pragma unroll
            for (int o = 16; o; o >>= 1) m = fmaxf(m, __shfl_xor_sync(0xffffffffu, m, o));
            float Z = 0.f;
#pragma unroll
            for (int r = 0; r < 7; r++) {
                float wv = (lane + 32 * r < P_) ? expf(acc[tt][r] * 0.125f - m) : 0.f;
                acc[tt][r] = wv;
                Z += wv;
            }
#pragma unroll
            for (int o = 16; o; o >>= 1) Z += __shfl_xor_sync(0xffffffffu, Z, o);
            rZ[tt] = 1.f / Z;
        }

        float ov00 = 0.f, ov01 = 0.f, ov10 = 0.f, ov11 = 0.f;
#pragma unroll
        for (int r = 0; r < 6; r++) {
            int pl = 32 * r;
            for (int sl = 0; sl < 32; sl++) {
                float w0 = __shfl_sync(0xffffffffu, acc[0][r], sl);
                float w1 = __shfl_sync(0xffffffffu, acc[1][r], sl);
                float v0 = Vs[(pl + sl) * KV_STRIDE + lane];
                float v1 = Vs[(pl + sl) * KV_STRIDE + lane + 32];
                ov00 += w0 * v0; ov01 += w0 * v1;
                ov10 += w1 * v0; ov11 += w1 * v1;
            }
        }
        for (int sl = 0; sl < P_ - 192; sl++) {
            float w0 = __shfl_sync(0xffffffffu, acc[0][6], sl);
            float w1 = __shfl_sync(0xffffffffu, acc[1][6], sl);
            float v0 = Vs[(192 + sl) * KV_STRIDE + lane];
            float v1 = Vs[(192 + sl) * KV_STRIDE + lane + 32];
            ov00 += w0 * v0; ov01 += w0 * v1;
            ov10 += w1 * v0; ov11 += w1 * v1;
        }
        size_t o0 = (size_t)(b * T_ + t0) * D_ + h * 64 + lane;
        size_t o1 = (size_t)(b * T_ + t0 + 1) * D_ + h * 64 + lane;
        store_split(outh, outl, o0,      ov00 * rZ[0]);
        store_split(outh, outl, o0 + 32, ov01 * rZ[0]);
        store_split(outh, outl, o1,      ov10 * rZ[1]);
        store_split(outh, outl, o1 + 32, ov11 * rZ[1]);
    }
}

// ---------------- fully fused GAT ----------------
template <int N, int ITILE>
__global__ void gat_fused_kernel(const float* __restrict__ Wh,
                                 const float* __restrict__ avec,
                                 const int* __restrict__ adj, int adjBatchStride,
                                 float* __restrict__ outmean) {
    constexpr int NPAD = 66;
    constexpr int NR = (N + 31) / 32;
    constexpr int MI = (ITILE + 7) / 8;
    int tile = blockIdx.x, h = blockIdx.y, b = blockIdx.z;
    int i0 = tile * ITILE;
    extern __shared__ float sm[];
    float* Whs  = sm;
    float* Ws   = Whs + N * NPAD;
    float* srcs = Ws + ITILE * N;
    float* dsts = srcs + N;
    float* zinv = dsts + N;
    float* as   = zinv + ITILE;
    int tid = threadIdx.x, lane = tid & 31, wid = tid >> 5;

    if (tid < 128) as[tid] = avec[tid];
    for (int idx = tid; idx < N * 64; idx += 256) {
        int j = idx >> 6, f = idx & 63;
        Whs[j * NPAD + f] = Wh[(size_t)(b * N + j) * D_ + h * 64 + f];
    }
    __syncthreads();

    for (int j = tid; j < N; j += 256) {
        float s = 0.f, d = 0.f;
#pragma unroll 8
        for (int f = 0; f < 64; f++) {
            float wv = Whs[j * NPAD + f];
            s += wv * as[f];
            d += wv * as[64 + f];
        }
        srcs[j] = s;
        dsts[j] = d;
    }
    __syncthreads();

    for (int iloc = wid; iloc < ITILE; iloc += 8) {
        int i = i0 + iloc;
        float si = srcs[i];
        float ev[NR];
        float m = -1e30f;
#pragma unroll
        for (int r = 0; r < NR; r++) {
            int j = lane + 32 * r;
            float e = -1e30f;
            if (j < N) {
                int a = adj[(size_t)b * adjBatchStride + (size_t)i * N + j];
                if (a > 0) {
                    float x = si + dsts[j];
                    e = x > 0.f ? x : 0.2f * x;
                }
            }
            ev[r] = e;
            m = fmaxf(m, e);
        }
#pragma unroll
        for (int o = 16; o; o >>= 1) m = fmaxf(m, __shfl_xor_sync(0xffffffffu, m, o));
        float Z = 0.f;
#pragma unroll
        for (int r = 0; r < NR; r++) {
            int j = lane + 32 * r;
            float wv = (ev[r] > -1e29f) ? expf(ev[r] - m) : 0.f;
            if (j < N) Ws[iloc * N + j] = wv;
            Z += wv;
        }
#pragma unroll
        for (int o = 16; o; o >>= 1) Z += __shfl_xor_sync(0xffffffffu, Z, o);
        if (lane == 0) zinv[iloc] = 1.f / Z;
    }
    __syncthreads();

    int f2 = lane * 2;
    float acc0[MI], acc1[MI];
#pragma unroll
    for (int m = 0; m < MI; m++) { acc0[m] = 0.f; acc1[m] = 0.f; }
    for (int j = 0; j < N; j++) {
        float2 wh = *(const float2*)&Whs[j * NPAD + f2];
#pragma unroll
        for (int m = 0; m < MI; m++) {
            int iloc = wid + 8 * m;
            float wv = (iloc < ITILE) ? Ws[iloc * N + j] : 0.f;
            acc0[m] += wv * wh.x;
            acc1[m] += wv * wh.y;
        }
    }
    float s0 = 0.f, s1 = 0.f;
#pragma unroll
    for (int m = 0; m < MI; m++) {
        int iloc = wid + 8 * m;
        if (iloc < ITILE) {
            float z = zinv[iloc];
            float v0 = acc0[m] * z, v1 = acc1[m] * z;
            v0 = v0 > 0.f ? v0 : expm1f(v0);
            v1 = v1 > 0.f ? v1 : expm1f(v1);
            s0 += v0;
            s1 += v1;
        }
    }
    atomicAdd(&outmean[b * D_ + h * 64 + f2],     s0 * (1.0f / N));
    atomicAdd(&outmean[b * D_ + h * 64 + f2 + 1], s1 * (1.0f / N));
}

// ---------------- f_token, s_token, f_global, cosine, head ----------------
__global__ void ftok_kernel(const float* __restrict__ upd, float* __restrict__ ftok) {
    int idx = blockIdx.x * 256 + threadIdx.x;
    int b = idx / D_, d = idx - b * D_;
    float s = 0.f;
    for (int t = 0; t < T_; t++) s += upd[(size_t)(b * T_ + t) * D_ + d];
    ftok[idx] = s * (1.0f / T_);
}
__global__ void stok_kernel(const float* __restrict__ upd, const float* __restrict__ img,
                            float* __restrict__ stok) {
    int gw = (blockIdx.x * 256 + threadIdx.x) >> 5;
    int lane = threadIdx.x & 31;
    int b = gw >> 6, t = gw & 63;
    float a = 0.f;
    for (int d = lane; d < D_; d += 32)
        a += upd[(size_t)(b * T_ + t) * D_ + d] * img[(size_t)(b * P_ + t) * D_ + d];
#pragma unroll
    for (int o = 16; o; o >>= 1) a += __shfl_xor_sync(0xffffffffu, a, o);
    if (lane == 0) atomicAdd(&stok[b], a * (1.0f / T_));
}
__global__ void fglobal_kernel(const float* __restrict__ ct, const float* __restrict__ Wp,
                               const float* __restrict__ bp, float* __restrict__ out) {
    int b = blockIdx.y;
    int n = blockIdx.x * 128 + threadIdx.x;
    float acc = bp[n];
    for (int k = 0; k < 512; k++) acc += ct[b * 512 + k] * Wp[(size_t)k * D_ + n];
    out[b * D_ + n] = acc;
}
__global__ void cos_kernel(const float* __restrict__ tgf, const float* __restrict__ igf,
                           const float* __restrict__ ct, const float* __restrict__ ci,
                           const float* __restrict__ ls,
                           float* __restrict__ sphr, float* __restrict__ sglob) {
    int b = blockIdx.x, tid = threadIdx.x;
    __shared__ float r0[256], r1[256], r2[256];
    float d0 = 0.f, d1 = 0.f, d2 = 0.f;
    for (int d = tid; d < D_; d += 256) {
        float x = tgf[b * D_ + d], y = igf[b * D_ + d];
        d0 += x * y; d1 += x * x; d2 += y * y;
    }
    r0[tid] = d0; r1[tid] = d1; r2[tid] = d2;
    __syncthreads();
    for (int o = 128; o; o >>= 1) {
        if (tid < o) { r0[tid] += r0[tid + o]; r1[tid] += r1[tid + o]; r2[tid] += r2[tid + o]; }
        __syncthreads();
    }
    if (tid == 0) {
        float nx = fmaxf(sqrtf(r1[0]), 1e-8f), ny = fmaxf(sqrtf(r2[0]), 1e-8f);
        sphr[b] = r0[0] / (nx * ny);
    }
    __syncthreads();
    d0 = d1 = d2 = 0.f;
    for (int d = tid; d < 512; d += 256) {
        float x = ct[b * 512 + d], y = ci[b * 512 + d];
        d0 += x * y; d1 += x * x; d2 += y * y;
    }
    r0[tid] = d0; r1[tid] = d1; r2[tid] = d2;
    __syncthreads();
    for (int o = 128; o; o >>= 1) {
        if (tid < o) { r0[tid] += r0[tid + o]; r1[tid] += r1[tid + o]; r2[tid] += r2[tid + o]; }
        __syncthreads();
    }
    if (tid == 0) {
        float nx = fmaxf(sqrtf(r1[0]), 1e-8f), ny = fmaxf(sqrtf(r2[0]), 1e-8f);
        sglob[b] = expf(*ls) * r0[0] / (nx * ny);
    }
}
__global__ void head_kernel(const float* __restrict__ stok, const float* __restrict__ sphr,
                            const float* __restrict__ sglob,
                            const float* __restrict__ f1w, const float* __restrict__ f1b,
                            const float* __restrict__ f2w, const float* __restrict__ f2b,
                            const float* __restrict__ ftok, const float* __restrict__ tgf,
                            const float* __restrict__ fglob,
                            const float* __restrict__ c1w, const float* __restrict__ c1b,
                            const float* __restrict__ c2w, const float* __restrict__ c2b,
                            float* __restrict__ out) {
    int b = blockIdx.x, tid = threadIdx.x;  // 384
    __shared__ float w3[3];
    __shared__ float fa[D_];
    __shared__ float red[768];
    if (tid == 0) {
        float s3[3] = {stok[b], sphr[b], sglob[b]};
        float h16[16];
        for (int j = 0; j < 16; j++) {
            float v = f1b[j];
            for (int i = 0; i < 3; i++) v += s3[i] * f1w[i * 16 + j];
            h16[j] = 0.5f * v * (1.0f + erff(v * 0.70710678118654752f));
        }
        for (int c = 0; c < 3; c++) {
            float v = f2b[c];
            for (int j = 0; j < 16; j++) v += h16[j] * f2w[j * 3 + c];
            w3[c] = 1.0f / (1.0f + expf(-v));
        }
    }
    __syncthreads();
    for (int d = tid; d < D_; d += 384)
        fa[d] = w3[0] * ftok[b * D_ + d] + w3[1] * tgf[b * D_ + d] + w3[2] * fglob[b * D_ + d];
    __syncthreads();
    float hj = c1b[tid];
    for (int d = 0; d < D_; d++) hj += fa[d] * c1w[(size_t)d * 384 + tid];
    hj = fmaxf(hj, 0.f);
    red[tid] = hj * c2w[tid * 2];
    red[384 + tid] = hj * c2w[tid * 2 + 1];
    __syncthreads();
    if (tid < 128) {
        red[tid] += red[tid + 128] + red[tid + 256];
        red[384 + tid] += red[384 + tid + 128] + red[384 + tid + 256];
    }
    __syncthreads();
    for (int o = 64; o; o >>= 1) {
        if (tid < o) { red[tid] += red[tid + o]; red[384 + tid] += red[384 + tid + o]; }
        __syncthreads();
    }
    if (tid == 0) {
        out[b * 2 + 0] = red[0] + c2b[0];
        out[b * 2 + 1] = red[384] + c2b[1];
    }
}

// ---------------- host launcher ----------------
extern "C" void kernel_launch(void* const* d_in, const int* in_sizes, int n_in,
                              void* d_out, int out_size) {
    const float* text       = (const float*)d_in[0];
    const float* image      = (const float*)d_in[1];
    const float* clip_text  = (const float*)d_in[2];
    const float* clip_image = (const float*)d_in[3];
    const float* logit_sc   = (const float*)d_in[4];
    const float* wq = (const float*)d_in[5];  const float* bq = (const float*)d_in[6];
    const float* wk = (const float*)d_in[7];  const float* bk = (const float*)d_in[8];
    const float* wv = (const float*)d_in[9];  const float* bv = (const float*)d_in[10];
    const float* wo = (const float*)d_in[11]; const float* bo = (const float*)d_in[12];
    const float* Wt = (const float*)d_in[13]; const float* at = (const float*)d_in[14];
    const float* Wi = (const float*)d_in[15]; const float* ai = (const float*)d_in[16];
    const float* Wp = (const float*)d_in[17]; const float* bp = (const float*)d_in[18];
    const float* f1w = (const float*)d_in[19]; const float* f1b = (const float*)d_in[20];
    const float* f2w = (const float*)d_in[21]; const float* f2b = (const float*)d_in[22];
    const float* c1w = (const float*)d_in[23]; const float* c1b = (const float*)d_in[24];
    const float* c2w = (const float*)d_in[25]; const float* c2b = (const float*)d_in[26];
    const int* text_adj  = (const int*)d_in[27];
    const int* image_adj = (const int*)d_in[28];
    float* out = (float*)d_out;

    float *p_q, *p_k, *p_v, *p_upd, *p_wht, *p_whi;
    float *p_tgf, *p_igf, *p_ftok, *p_fglob, *p_stok, *p_sphr, *p_sglob;
    __nv_bfloat16 *p_th, *p_tl, *p_ih, *p_il, *p_ath, *p_atl, *p_wh6, *p_wl6;
    cudaGetSymbolAddress((void**)&p_q, g_q);
    cudaGetSymbolAddress((void**)&p_k, g_k);
    cudaGetSymbolAddress((void**)&p_v, g_v);
    cudaGetSymbolAddress((void**)&p_upd, g_upd);
    cudaGetSymbolAddress((void**)&p_wht, g_wht);
    cudaGetSymbolAddress((void**)&p_whi, g_whi);
    cudaGetSymbolAddress((void**)&p_tgf, g_tgf);
    cudaGetSymbolAddress((void**)&p_igf, g_igf);
    cudaGetSymbolAddress((void**)&p_ftok, g_ftok);
    cudaGetSymbolAddress((void**)&p_fglob, g_fglob);
    cudaGetSymbolAddress((void**)&p_stok, g_stok);
    cudaGetSymbolAddress((void**)&p_sphr, g_sphr);
    cudaGetSymbolAddress((void**)&p_sglob, g_sglob);
    cudaGetSymbolAddress((void**)&p_th, g_th);
    cudaGetSymbolAddress((void**)&p_tl, g_tl);
    cudaGetSymbolAddress((void**)&p_ih, g_ih);
    cudaGetSymbolAddress((void**)&p_il, g_il);
    cudaGetSymbolAddress((void**)&p_ath, g_ath);
    cudaGetSymbolAddress((void**)&p_atl, g_atl);
    cudaGetSymbolAddress((void**)&p_wh6, g_wh6);
    cudaGetSymbolAddress((void**)&p_wl6, g_wl6);

    static cudaStream_t s1 = nullptr, s2 = nullptr;
    static cudaEvent_t eFork = nullptr, eS1 = nullptr, eS2 = nullptr;
    if (!s1) {
        cudaStreamCreateWithFlags(&s1, cudaStreamNonBlocking);
        cudaStreamCreateWithFlags(&s2, cudaStreamNonBlocking);
        cudaEventCreateWithFlags(&eFork, cudaEventDisableTiming);
        cudaEventCreateWithFlags(&eS1, cudaEventDisableTiming);
        cudaEventCreateWithFlags(&eS2, cudaEventDisableTiming);
    }

    const int gatI_smem = (P_ * 66 + 49 * P_ + 2 * P_ + 49 + 128) * 4;
    const int gatT_smem = (T_ * 66 + 64 * T_ + 2 * T_ + 64 + 128) * 4;
    cudaFuncSetAttribute(bf16_gemm_kernel, cudaFuncAttributeMaxDynamicSharedMemorySize, GEMM_SMEM);
    cudaFuncSetAttribute(attn_kernel, cudaFuncAttributeMaxDynamicSharedMemorySize, ATTN_SMEM);
    cudaFuncSetAttribute(gat_fused_kernel<P_, 49>, cudaFuncAttributeMaxDynamicSharedMemorySize, gatI_smem);
    cudaFuncSetAttribute(gat_fused_kernel<T_, 64>, cudaFuncAttributeMaxDynamicSharedMemorySize, gatT_smem);

    // ---- main stream: zero + splits ----
    zero3_kernel<<<(B_ * D_ + 255) / 256, 256>>>(p_tgf, p_igf, p_stok, B_ * D_, B_);
    split_kernel<<<(B_ * T_ * D_ / 4 + 255) / 256, 256>>>(text, p_th, p_tl, B_ * T_ * D_ / 4);
    split_kernel<<<(B_ * P_ * D_ / 4 + 255) / 256, 256>>>(image, p_ih, p_il, B_ * P_ * D_ / 4);
    {
        SixPtr sp;
        sp.s[0] = wq; sp.s[1] = wk; sp.s[2] = wv; sp.s[3] = wo; sp.s[4] = Wt; sp.s[5] = Wi;
        sp.h = p_wh6; sp.l = p_wl6;
        split6_kernel<<<dim3((D_ * D_ / 4 + 255) / 256, 6), 256>>>(sp, D_ * D_ / 4);
    }
    cudaEventRecord(eFork, 0);
    cudaStreamWaitEvent(s1, eFork, 0);
    cudaStreamWaitEvent(s2, eFork, 0);

    const size_t WSZ = (size_t)D_ * D_;
    // ---- s1: v (big), q (small) ----
    bf16_gemm_kernel<<<dim3(6, 49), 256, GEMM_SMEM, s1>>>(p_ih, p_il, p_wh6 + 2 * WSZ, p_wl6 + 2 * WSZ, bv, p_v, B_ * P_);
    bf16_gemm_kernel<<<dim3(6, 16), 256, GEMM_SMEM, s1>>>(p_th, p_tl, p_wh6 + 0 * WSZ, p_wl6 + 0 * WSZ, bq, p_q, B_ * T_);
    cudaEventRecord(eS1, s1);

    // ---- s2: whi (big), wht (small), GATs, cos ----
    bf16_gemm_kernel<<<dim3(6, 49), 256, GEMM_SMEM, s2>>>(p_ih, p_il, p_wh6 + 5 * WSZ, p_wl6 + 5 * WSZ, nullptr, p_whi, B_ * P_);
    bf16_gemm_kernel<<<dim3(6, 16), 256, GEMM_SMEM, s2>>>(p_th, p_tl, p_wh6 + 4 * WSZ, p_wl6 + 4 * WSZ, nullptr, p_wht, B_ * T_);
    gat_fused_kernel<T_, 64><<<dim3(1, H_, B_), 256, gatT_smem, s2>>>(p_wht, at, text_adj, T_ * T_, p_tgf);
    gat_fused_kernel<P_, 49><<<dim3(4, H_, B_), 256, gatI_smem, s2>>>(p_whi, ai, image_adj, 0, p_igf);
    cos_kernel<<<B_, 256, 0, s2>>>(p_tgf, p_igf, clip_text, clip_image, logit_sc, p_sphr, p_sglob);
    cudaEventRecord(eS2, s2);

    // ---- main: k (big) -> attn -> upd -> tail ----
    bf16_gemm_kernel<<<dim3(6, 49), 256, GEMM_SMEM>>>(p_ih, p_il, p_wh6 + 1 * WSZ, p_wl6 + 1 * WSZ, bk, p_k, B_ * P_);
    cudaStreamWaitEvent((cudaStream_t)0, eS1, 0);
    attn_kernel<<<dim3(H_, B_), 256, ATTN_SMEM>>>(p_q, p_k, p_v, p_ath, p_atl);
    bf16_gemm_kernel<<<dim3(6, 16), 256, GEMM_SMEM>>>(p_ath, p_atl, p_wh6 + 3 * WSZ, p_wl6 + 3 * WSZ, bo, p_upd, B_ * T_);
    ftok_kernel<<<(B_ * D_) / 256, 256>>>(p_upd, p_ftok);
    stok_kernel<<<(B_ * T_ * 32) / 256, 256>>>(p_upd, image, p_stok);
    fglobal_kernel<<<dim3(6, B_), 128>>>(clip_text, Wp, bp, p_fglob);
    cudaStreamWaitEvent((cudaStream_t)0, eS2, 0);
    head_kernel<<<B_, 384>>>(p_stok, p_sphr, p_sglob, f1w, f1b, f2w, f2b,
                             p_ftok, p_tgf, p_fglob, c1w, c1b, c2w, c2b, out);
}

// round 13
// speedup vs baseline: 3.2506x; 1.0643x over previous
#include <cuda_runtime.h>
#include <cuda_bf16.h>
#include <mma.h>
#include <math.h>
#include <stdint.h>

using namespace nvcuda;

// Problem constants
#define B_  32
#define T_  64
#define P_  196
#define D_  768
#define H_  12
#define HD_ 64

// ---------------- scratch (static device globals; no allocations) ----------------
__device__ float g_q   [B_*T_*D_];
__device__ float g_k   [B_*P_*D_];
__device__ float g_v   [B_*P_*D_];
__device__ float g_upd [B_*T_*D_];
__device__ float g_wht [B_*T_*D_];
__device__ float g_whi [B_*P_*D_];
__device__ float g_tgf[B_*D_], g_igf[B_*D_], g_ftok[B_*D_], g_fglob[B_*D_];
__device__ float g_stok[B_], g_sphr[B_], g_sglob[B_];
// bf16 hi/lo splits
__device__ __nv_bfloat16 g_th[B_*T_*D_], g_tl[B_*T_*D_];
__device__ __nv_bfloat16 g_ih[B_*P_*D_], g_il[B_*P_*D_];
__device__ __nv_bfloat16 g_ath[B_*T_*D_], g_atl[B_*T_*D_];
__device__ __nv_bfloat16 g_wh6[6][D_*D_], g_wl6[6][D_*D_];

// ---------------- helpers ----------------
__device__ __forceinline__ uint32_t smem_u32(const void* p) {
    uint32_t a;
    asm("{ .reg .u64 t; cvta.to.shared.u64 t, %1; cvt.u32.u64 %0, t; }" : "=r"(a) : "l"(p));
    return a;
}
__device__ __forceinline__ void cp16(uint32_t dst, const void* src) {
    asm volatile("cp.async.cg.shared.global [%0], [%1], 16;\n" :: "r"(dst), "l"(src));
}
// fp32 -> (hi bf16x2, lo bf16x2) split for a float4 (memory order)
__device__ __forceinline__ void cvt_split4(float4 v, uint2& hi, uint2& lo) {
    uint32_t h0, h1;
    asm("cvt.rn.bf16x2.f32 %0, %1, %2;" : "=r"(h0) : "f"(v.y), "f"(v.x));
    asm("cvt.rn.bf16x2.f32 %0, %1, %2;" : "=r"(h1) : "f"(v.w), "f"(v.z));
    float r0 = v.x - __uint_as_float(h0 << 16);
    float r1 = v.y - __uint_as_float(h0 & 0xFFFF0000u);
    float r2 = v.z - __uint_as_float(h1 << 16);
    float r3 = v.w - __uint_as_float(h1 & 0xFFFF0000u);
    uint32_t l0, l1;
    asm("cvt.rn.bf16x2.f32 %0, %1, %2;" : "=r"(l0) : "f"(r1), "f"(r0));
    asm("cvt.rn.bf16x2.f32 %0, %1, %2;" : "=r"(l1) : "f"(r3), "f"(r2));
    hi = make_uint2(h0, h1);
    lo = make_uint2(l0, l1);
}

// ---------------- split kernel ----------------
__global__ void split_kernel(const float* __restrict__ src, __nv_bfloat16* __restrict__ dh,
                             __nv_bfloat16* __restrict__ dl, int n4) {
    int i = blockIdx.x * 256 + threadIdx.x;
    if (i < n4) {
        float4 v = ((const float4*)src)[i];
        uint2 hi, lo;
        cvt_split4(v, hi, lo);
        ((uint2*)dh)[i] = hi;
        ((uint2*)dl)[i] = lo;
    }
}

__global__ void zero3_kernel(float* a, float* b, float* c, int n, int nc) {
    int i = blockIdx.x * blockDim.x + threadIdx.x;
    if (i < n) { a[i] = 0.f; b[i] = 0.f; }
    if (i < nc) c[i] = 0.f;
}

// ---------------- bf16-split GEMM (pre-split operands, cp.async 3-stage) ----------
// C[M,768] = A @ W (+bias), C ~= Ah*Wh + Ah*Wl + Al*Wh, fp32 accum.
// CTA 128x128, 8 warps (2x4), warp tile 64x32 (4x2 frags), K-chunks of 32.
// 3 smem stages (113.7 KB) + <=128 regs -> 2 CTAs/SM -> big GEMM in ONE wave.
#define LDAs 40
#define LDBs 136
#define ASZ (128 * LDAs)               // 5120 bf16
#define BSZ (32 * LDBs)                // 4352 bf16
#define STG (2 * ASZ + 2 * BSZ)        // 18944 bf16 per stage
#define GEMM_SMEM (3 * STG * 2)        // 113664 bytes

__global__ __launch_bounds__(256, 2)
void bf16_gemm_kernel(const __nv_bfloat16* __restrict__ Ah, const __nv_bfloat16* __restrict__ Al,
                      const __nv_bfloat16* __restrict__ Wh, const __nv_bfloat16* __restrict__ Wl,
                      const float* __restrict__ bias, float* __restrict__ C, int M) {
    constexpr int K = 768, N = 768;
    extern __shared__ __align__(1024) uint8_t dsm[];
    int tid = threadIdx.x, wid = tid >> 5;
    int warp_m = wid & 1, warp_n = wid >> 1;
    int m0 = blockIdx.y * 128, n0 = blockIdx.x * 128;
    uint32_t sb = smem_u32(dsm);

    wmma::fragment<wmma::accumulator, 16, 16, 16, float> acc[4][2];
#pragma unroll
    for (int i = 0; i < 4; i++)
#pragma unroll
        for (int j = 0; j < 2; j++) wmma::fill_fragment(acc[i][j], 0.f);

    auto issue = [&](int c) {
        int kc = c * 32;
        uint32_t st = sb + (uint32_t)(c % 3) * (STG * 2);
#pragma unroll
        for (int s = 0; s < 2; s++) {
            const __nv_bfloat16* g = s ? Al : Ah;
            uint32_t d0 = st + s * (ASZ * 2);
#pragma unroll
            for (int i = 0; i < 2; i++) {
                int q = i * 256 + tid;             // 0..511
                int row = q >> 2, kcol = (q & 3) << 3;
                cp16(d0 + (uint32_t)(row * LDAs + kcol) * 2,
                     g + (size_t)(m0 + row) * K + kc + kcol);
            }
        }
#pragma unroll
        for (int s = 0; s < 2; s++) {
            const __nv_bfloat16* g = s ? Wl : Wh;
            uint32_t d0 = st + (2 * ASZ + s * BSZ) * 2;
#pragma unroll
            for (int i = 0; i < 2; i++) {
                int q = i * 256 + tid;             // 0..511
                int row = q >> 4, col = (q & 15) << 3;
                cp16(d0 + (uint32_t)(row * LDBs + col) * 2,
                     g + (size_t)(kc + row) * N + n0 + col);
            }
        }
        asm volatile("cp.async.commit_group;\n" ::);
    };

    issue(0); issue(1);

    for (int c = 0; c < 24; c++) {
        if (c < 23) asm volatile("cp.async.wait_group 1;\n" ::);
        else        asm volatile("cp.async.wait_group 0;\n" ::);
        __syncthreads();
        if (c + 2 < 24) issue(c + 2);   // into buffer (c+2)%3 == (c-1)%3, already consumed
        const __nv_bfloat16* st = (const __nv_bfloat16*)(dsm + (size_t)(c % 3) * (STG * 2));
        const __nv_bfloat16* Ahs = st;
        const __nv_bfloat16* Als = st + ASZ;
        const __nv_bfloat16* Bhs = st + 2 * ASZ;
        const __nv_bfloat16* Bls = st + 2 * ASZ + BSZ;
#pragma unroll
        for (int ks = 0; ks < 32; ks += 16) {
            wmma::fragment<wmma::matrix_b, 16, 16, 16, __nv_bfloat16, wmma::row_major> fbh[2], fbl[2];
#pragma unroll
            for (int j = 0; j < 2; j++) {
                wmma::load_matrix_sync(fbh[j], Bhs + ks * LDBs + warp_n * 32 + j * 16, LDBs);
                wmma::load_matrix_sync(fbl[j], Bls + ks * LDBs + warp_n * 32 + j * 16, LDBs);
            }
#pragma unroll
            for (int i = 0; i < 4; i++) {
                wmma::fragment<wmma::matrix_a, 16, 16, 16, __nv_bfloat16, wmma::row_major> fah, fal;
                wmma::load_matrix_sync(fah, Ahs + (warp_m * 64 + i * 16) * LDAs + ks, LDAs);
                wmma::load_matrix_sync(fal, Als + (warp_m * 64 + i * 16) * LDAs + ks, LDAs);
#pragma unroll
                for (int j = 0; j < 2; j++) {
                    wmma::mma_sync(acc[i][j], fah, fbh[j], acc[i][j]);
                    wmma::mma_sync(acc[i][j], fah, fbl[j], acc[i][j]);
                    wmma::mma_sync(acc[i][j], fal, fbh[j], acc[i][j]);
                }
            }
        }
    }
    __syncthreads();

    // epilogue: accum -> smem -> coalesced gmem + bias
    float* ep = (float*)dsm;
#pragma unroll
    for (int i = 0; i < 4; i++)
#pragma unroll
        for (int j = 0; j < 2; j++)
            wmma::store_matrix_sync(ep + (warp_m * 64 + i * 16) * 136 + warp_n * 32 + j * 16,
                                    acc[i][j], 136, wmma::mem_row_major);
    __syncthreads();
    int cq = (tid & 31) << 2;
    float4 bb = make_float4(0.f, 0.f, 0.f, 0.f);
    if (bias) bb = *(const float4*)(bias + n0 + cq);
#pragma unroll
    for (int i = 0; i < 16; i++) {
        int r = i * 8 + (tid >> 5);
        float4 o = *(float4*)(ep + r * 136 + cq);
        o.x += bb.x; o.y += bb.y; o.z += bb.z; o.w += bb.w;
        *(float4*)(C + (size_t)(m0 + r) * N + n0 + cq) = o;
    }
}

// ---------------- cross attention: per (b,h); warp-per-2-timesteps ----------------
#define KV_STRIDE 66
#define ATTN_SMEM ((2 * P_ * KV_STRIDE + 8 * 132) * 4)
__device__ __forceinline__ void store_split(__nv_bfloat16* ph, __nv_bfloat16* pl,
                                            size_t idx, float v) {
    __nv_bfloat16 hb = __float2bfloat16(v);
    float hf = __bfloat162float(hb);
    ph[idx] = hb;
    pl[idx] = __float2bfloat16(v - hf);
}
__global__ void attn_kernel(const float* __restrict__ q, const float* __restrict__ k,
                            const float* __restrict__ v,
                            __nv_bfloat16* __restrict__ outh, __nv_bfloat16* __restrict__ outl) {
    int h = blockIdx.x, b = blockIdx.y;
    extern __shared__ float sm[];
    float* Ks = sm;
    float* Vs = Ks + P_ * KV_STRIDE;
    float* qs = Vs + P_ * KV_STRIDE;
    int tid = threadIdx.x, lane = tid & 31, w = tid >> 5;

    for (int idx = tid; idx < P_ * 64; idx += 256) {
        int p = idx >> 6, d = idx & 63;
        size_t g = (size_t)(b * P_ + p) * D_ + h * 64 + d;
        Ks[p * KV_STRIDE + d] = k[g];
        Vs[p * KV_STRIDE + d] = v[g];
    }
    __syncthreads();

    float* myq = qs + w * 132;
    int ro[7];
#pragma unroll
    for (int r = 0; r < 7; r++) {
        int p = lane + 32 * r;
        ro[r] = (p < P_ ? p : P_ - 1) * KV_STRIDE;
    }

    for (int s = 0; s < 4; s++) {
        int t0 = w * 8 + s * 2;
        __syncwarp();
        myq[lane]       = q[(size_t)(b * T_ + t0) * D_ + h * 64 + lane];
        myq[lane + 32]  = q[(size_t)(b * T_ + t0) * D_ + h * 64 + lane + 32];
        myq[66 + lane]      = q[(size_t)(b * T_ + t0 + 1) * D_ + h * 64 + lane];
        myq[66 + lane + 32] = q[(size_t)(b * T_ + t0 + 1) * D_ + h * 64 + lane + 32];
        __syncwarp();

        float acc[2][7];
#pragma unroll
        for (int r = 0; r < 7; r++) { acc[0][r] = 0.f; acc[1][r] = 0.f; }
        for (int d = 0; d < 64; d++) {
            float q0 = myq[d], q1 = myq[66 + d];
#pragma unroll
            for (int r = 0; r < 7; r++) {
                float kv = Ks[ro[r] + d];
                acc[0][r] += q0 * kv;
                acc[1][r] += q1 * kv;
            }
        }

        float rZ[2];
#pragma unroll
        for (int tt = 0; tt < 2; tt++) {
            float m = -1e30f;
#pragma unroll
            for (int r = 0; r < 7; r++)
                if (lane + 32 * r < P_) m = fmaxf(m, acc[tt][r] * 0.125f);
#pragma unroll
            for (int o = 16; o; o >>= 1) m = fmaxf(m, __shfl_xor_sync(0xffffffffu, m, o));
            float Z = 0.f;
#pragma unroll
            for (int r = 0; r < 7; r++) {
                float wv = (lane + 32 * r < P_) ? expf(acc[tt][r] * 0.125f - m) : 0.f;
                acc[tt][r] = wv;
                Z += wv;
            }
#pragma unroll
            for (int o = 16; o; o >>= 1) Z += __shfl_xor_sync(0xffffffffu, Z, o);
            rZ[tt] = 1.f / Z;
        }

        float ov00 = 0.f, ov01 = 0.f, ov10 = 0.f, ov11 = 0.f;
#pragma unroll
        for (int r = 0; r < 6; r++) {
            int pl = 32 * r;
            for (int sl = 0; sl < 32; sl++) {
                float w0 = __shfl_sync(0xffffffffu, acc[0][r], sl);
                float w1 = __shfl_sync(0xffffffffu, acc[1][r], sl);
                float v0 = Vs[(pl + sl) * KV_STRIDE + lane];
                float v1 = Vs[(pl + sl) * KV_STRIDE + lane + 32];
                ov00 += w0 * v0; ov01 += w0 * v1;
                ov10 += w1 * v0; ov11 += w1 * v1;
            }
        }
        for (int sl = 0; sl < P_ - 192; sl++) {
            float w0 = __shfl_sync(0xffffffffu, acc[0][6], sl);
            float w1 = __shfl_sync(0xffffffffu, acc[1][6], sl);
            float v0 = Vs[(192 + sl) * KV_STRIDE + lane];
            float v1 = Vs[(192 + sl) * KV_STRIDE + lane + 32];
            ov00 += w0 * v0; ov01 += w0 * v1;
            ov10 += w1 * v0; ov11 += w1 * v1;
        }
        size_t o0 = (size_t)(b * T_ + t0) * D_ + h * 64 + lane;
        size_t o1 = (size_t)(b * T_ + t0 + 1) * D_ + h * 64 + lane;
        store_split(outh, outl, o0,      ov00 * rZ[0]);
        store_split(outh, outl, o0 + 32, ov01 * rZ[0]);
        store_split(outh, outl, o1,      ov10 * rZ[1]);
        store_split(outh, outl, o1 + 32, ov11 * rZ[1]);
    }
}

// ---------------- fully fused GAT ----------------
template <int N, int ITILE>
__global__ void gat_fused_kernel(const float* __restrict__ Wh,
                                 const float* __restrict__ avec,
                                 const int* __restrict__ adj, int adjBatchStride,
                                 float* __restrict__ outmean) {
    constexpr int NPAD = 66;
    constexpr int NR = (N + 31) / 32;
    constexpr int MI = (ITILE + 7) / 8;
    int tile = blockIdx.x, h = blockIdx.y, b = blockIdx.z;
    int i0 = tile * ITILE;
    extern __shared__ float sm[];
    float* Whs  = sm;
    float* Ws   = Whs + N * NPAD;
    float* srcs = Ws + ITILE * N;
    float* dsts = srcs + N;
    float* zinv = dsts + N;
    float* as   = zinv + ITILE;
    int tid = threadIdx.x, lane = tid & 31, wid = tid >> 5;

    if (tid < 128) as[tid] = avec[tid];
    for (int idx = tid; idx < N * 64; idx += 256) {
        int j = idx >> 6, f = idx & 63;
        Whs[j * NPAD + f] = Wh[(size_t)(b * N + j) * D_ + h * 64 + f];
    }
    __syncthreads();

    for (int j = tid; j < N; j += 256) {
        float s = 0.f, d = 0.f;
#pragma unroll 8
        for (int f = 0; f < 64; f++) {
            float wv = Whs[j * NPAD + f];
            s += wv * as[f];
            d += wv * as[64 + f];
        }
        srcs[j] = s;
        dsts[j] = d;
    }
    __syncthreads();

    for (int iloc = wid; iloc < ITILE; iloc += 8) {
        int i = i0 + iloc;
        float si = srcs[i];
        float ev[NR];
        float m = -1e30f;
#pragma unroll
        for (int r = 0; r < NR; r++) {
            int j = lane + 32 * r;
            float e = -1e30f;
            if (j < N) {
                int a = adj[(size_t)b * adjBatchStride + (size_t)i * N + j];
                if (a > 0) {
                    float x = si + dsts[j];
                    e = x > 0.f ? x : 0.2f * x;
                }
            }
            ev[r] = e;
            m = fmaxf(m, e);
        }
#pragma unroll
        for (int o = 16; o; o >>= 1) m = fmaxf(m, __shfl_xor_sync(0xffffffffu, m, o));
        float Z = 0.f;
#pragma unroll
        for (int r = 0; r < NR; r++) {
            int j = lane + 32 * r;
            float wv = (ev[r] > -1e29f) ? expf(ev[r] - m) : 0.f;
            if (j < N) Ws[iloc * N + j] = wv;
            Z += wv;
        }
#pragma unroll
        for (int o = 16; o; o >>= 1) Z += __shfl_xor_sync(0xffffffffu, Z, o);
        if (lane == 0) zinv[iloc] = 1.f / Z;
    }
    __syncthreads();

    int f2 = lane * 2;
    float acc0[MI], acc1[MI];
#pragma unroll
    for (int m = 0; m < MI; m++) { acc0[m] = 0.f; acc1[m] = 0.f; }
    for (int j = 0; j < N; j++) {
        float2 wh = *(const float2*)&Whs[j * NPAD + f2];
#pragma unroll
        for (int m = 0; m < MI; m++) {
            int iloc = wid + 8 * m;
            float wv = (iloc < ITILE) ? Ws[iloc * N + j] : 0.f;
            acc0[m] += wv * wh.x;
            acc1[m] += wv * wh.y;
        }
    }
    float s0 = 0.f, s1 = 0.f;
#pragma unroll
    for (int m = 0; m < MI; m++) {
        int iloc = wid + 8 * m;
        if (iloc < ITILE) {
            float z = zinv[iloc];
            float v0 = acc0[m] * z, v1 = acc1[m] * z;
            v0 = v0 > 0.f ? v0 : expm1f(v0);
            v1 = v1 > 0.f ? v1 : expm1f(v1);
            s0 += v0;
            s1 += v1;
        }
    }
    atomicAdd(&outmean[b * D_ + h * 64 + f2],     s0 * (1.0f / N));
    atomicAdd(&outmean[b * D_ + h * 64 + f2 + 1], s1 * (1.0f / N));
}

// ---------------- f_token, s_token, f_global, cosine, head ----------------
__global__ void ftok_kernel(const float* __restrict__ upd, float* __restrict__ ftok) {
    int idx = blockIdx.x * 256 + threadIdx.x;
    int b = idx / D_, d = idx - b * D_;
    float s = 0.f;
    for (int t = 0; t < T_; t++) s += upd[(size_t)(b * T_ + t) * D_ + d];
    ftok[idx] = s * (1.0f / T_);
}
__global__ void stok_kernel(const float* __restrict__ upd, const float* __restrict__ img,
                            float* __restrict__ stok) {
    int gw = (blockIdx.x * 256 + threadIdx.x) >> 5;
    int lane = threadIdx.x & 31;
    int b = gw >> 6, t = gw & 63;
    float a = 0.f;
    for (int d = lane; d < D_; d += 32)
        a += upd[(size_t)(b * T_ + t) * D_ + d] * img[(size_t)(b * P_ + t) * D_ + d];
#pragma unroll
    for (int o = 16; o; o >>= 1) a += __shfl_xor_sync(0xffffffffu, a, o);
    if (lane == 0) atomicAdd(&stok[b], a * (1.0f / T_));
}
__global__ void fglobal_kernel(const float* __restrict__ ct, const float* __restrict__ Wp,
                               const float* __restrict__ bp, float* __restrict__ out) {
    int b = blockIdx.y;
    int n = blockIdx.x * 128 + threadIdx.x;
    float acc = bp[n];
    for (int k = 0; k < 512; k++) acc += ct[b * 512 + k] * Wp[(size_t)k * D_ + n];
    out[b * D_ + n] = acc;
}
__global__ void cos_kernel(const float* __restrict__ tgf, const float* __restrict__ igf,
                           const float* __restrict__ ct, const float* __restrict__ ci,
                           const float* __restrict__ ls,
                           float* __restrict__ sphr, float* __restrict__ sglob) {
    int b = blockIdx.x, tid = threadIdx.x;
    __shared__ float r0[256], r1[256], r2[256];
    float d0 = 0.f, d1 = 0.f, d2 = 0.f;
    for (int d = tid; d < D_; d += 256) {
        float x = tgf[b * D_ + d], y = igf[b * D_ + d];
        d0 += x * y; d1 += x * x; d2 += y * y;
    }
    r0[tid] = d0; r1[tid] = d1; r2[tid] = d2;
    __syncthreads();
    for (int o = 128; o; o >>= 1) {
        if (tid < o) { r0[tid] += r0[tid + o]; r1[tid] += r1[tid + o]; r2[tid] += r2[tid + o]; }
        __syncthreads();
    }
    if (tid == 0) {
        float nx = fmaxf(sqrtf(r1[0]), 1e-8f), ny = fmaxf(sqrtf(r2[0]), 1e-8f);
        sphr[b] = r0[0] / (nx * ny);
    }
    __syncthreads();
    d0 = d1 = d2 = 0.f;
    for (int d = tid; d < 512; d += 256) {
        float x = ct[b * 512 + d], y = ci[b * 512 + d];
        d0 += x * y; d1 += x * x; d2 += y * y;
    }
    r0[tid] = d0; r1[tid] = d1; r2[tid] = d2;
    __syncthreads();
    for (int o = 128; o; o >>= 1) {
        if (tid < o) { r0[tid] += r0[tid + o]; r1[tid] += r1[tid + o]; r2[tid] += r2[tid + o]; }
        __syncthreads();
    }
    if (tid == 0) {
        float nx = fmaxf(sqrtf(r1[0]), 1e-8f), ny = fmaxf(sqrtf(r2[0]), 1e-8f);
        sglob[b] = expf(*ls) * r0[0] / (nx * ny);
    }
}
__global__ void head_kernel(const float* __restrict__ stok, const float* __restrict__ sphr,
                            const float* __restrict__ sglob,
                            const float* __restrict__ f1w, const float* __restrict__ f1b,
                            const float* __restrict__ f2w, const float* __restrict__ f2b,
                            const float* __restrict__ ftok, const float* __restrict__ tgf,
                            const float* __restrict__ fglob,
                            const float* __restrict__ c1w, const float* __restrict__ c1b,
                            const float* __restrict__ c2w, const float* __restrict__ c2b,
                            float* __restrict__ out) {
    int b = blockIdx.x, tid = threadIdx.x;  // 384
    __shared__ float w3[3];
    __shared__ float fa[D_];
    __shared__ float red[768];
    if (tid == 0) {
        float s3[3] = {stok[b], sphr[b], sglob[b]};
        float h16[16];
        for (int j = 0; j < 16; j++) {
            float v = f1b[j];
            for (int i = 0; i < 3; i++) v += s3[i] * f1w[i * 16 + j];
            h16[j] = 0.5f * v * (1.0f + erff(v * 0.70710678118654752f));
        }
        for (int c = 0; c < 3; c++) {
            float v = f2b[c];
            for (int j = 0; j < 16; j++) v += h16[j] * f2w[j * 3 + c];
            w3[c] = 1.0f / (1.0f + expf(-v));
        }
    }
    __syncthreads();
    for (int d = tid; d < D_; d += 384)
        fa[d] = w3[0] * ftok[b * D_ + d] + w3[1] * tgf[b * D_ + d] + w3[2] * fglob[b * D_ + d];
    __syncthreads();
    float hj = c1b[tid];
    for (int d = 0; d < D_; d++) hj += fa[d] * c1w[(size_t)d * 384 + tid];
    hj = fmaxf(hj, 0.f);
    red[tid] = hj * c2w[tid * 2];
    red[384 + tid] = hj * c2w[tid * 2 + 1];
    __syncthreads();
    if (tid < 128) {
        red[tid] += red[tid + 128] + red[tid + 256];
        red[384 + tid] += red[384 + tid + 128] + red[384 + tid + 256];
    }
    __syncthreads();
    for (int o = 64; o; o >>= 1) {
        if (tid < o) { red[tid] += red[tid + o]; red[384 + tid] += red[384 + tid + o]; }
        __syncthreads();
    }
    if (tid == 0) {
        out[b * 2 + 0] = red[0] + c2b[0];
        out[b * 2 + 1] = red[384] + c2b[1];
    }
}

// ---------------- host launcher ----------------
extern "C" void kernel_launch(void* const* d_in, const int* in_sizes, int n_in,
                              void* d_out, int out_size) {
    const float* text       = (const float*)d_in[0];
    const float* image      = (const float*)d_in[1];
    const float* clip_text  = (const float*)d_in[2];
    const float* clip_image = (const float*)d_in[3];
    const float* logit_sc   = (const float*)d_in[4];
    const float* wq = (const float*)d_in[5];  const float* bq = (const float*)d_in[6];
    const float* wk = (const float*)d_in[7];  const float* bk = (const float*)d_in[8];
    const float* wv = (const float*)d_in[9];  const float* bv = (const float*)d_in[10];
    const float* wo = (const float*)d_in[11]; const float* bo = (const float*)d_in[12];
    const float* Wt = (const float*)d_in[13]; const float* at = (const float*)d_in[14];
    const float* Wi = (const float*)d_in[15]; const float* ai = (const float*)d_in[16];
    const float* Wp = (const float*)d_in[17]; const float* bp = (const float*)d_in[18];
    const float* f1w = (const float*)d_in[19]; const float* f1b = (const float*)d_in[20];
    const float* f2w = (const float*)d_in[21]; const float* f2b = (const float*)d_in[22];
    const float* c1w = (const float*)d_in[23]; const float* c1b = (const float*)d_in[24];
    const float* c2w = (const float*)d_in[25]; const float* c2b = (const float*)d_in[26];
    const int* text_adj  = (const int*)d_in[27];
    const int* image_adj = (const int*)d_in[28];
    float* out = (float*)d_out;

    float *p_q, *p_k, *p_v, *p_upd, *p_wht, *p_whi;
    float *p_tgf, *p_igf, *p_ftok, *p_fglob, *p_stok, *p_sphr, *p_sglob;
    __nv_bfloat16 *p_th, *p_tl, *p_ih, *p_il, *p_ath, *p_atl, *p_wh6, *p_wl6;
    cudaGetSymbolAddress((void**)&p_q, g_q);
    cudaGetSymbolAddress((void**)&p_k, g_k);
    cudaGetSymbolAddress((void**)&p_v, g_v);
    cudaGetSymbolAddress((void**)&p_upd, g_upd);
    cudaGetSymbolAddress((void**)&p_wht, g_wht);
    cudaGetSymbolAddress((void**)&p_whi, g_whi);
    cudaGetSymbolAddress((void**)&p_tgf, g_tgf);
    cudaGetSymbolAddress((void**)&p_igf, g_igf);
    cudaGetSymbolAddress((void**)&p_ftok, g_ftok);
    cudaGetSymbolAddress((void**)&p_fglob, g_fglob);
    cudaGetSymbolAddress((void**)&p_stok, g_stok);
    cudaGetSymbolAddress((void**)&p_sphr, g_sphr);
    cudaGetSymbolAddress((void**)&p_sglob, g_sglob);
    cudaGetSymbolAddress((void**)&p_th, g_th);
    cudaGetSymbolAddress((void**)&p_tl, g_tl);
    cudaGetSymbolAddress((void**)&p_ih, g_ih);
    cudaGetSymbolAddress((void**)&p_il, g_il);
    cudaGetSymbolAddress((void**)&p_ath, g_ath);
    cudaGetSymbolAddress((void**)&p_atl, g_atl);
    cudaGetSymbolAddress((void**)&p_wh6, g_wh6);
    cudaGetSymbolAddress((void**)&p_wl6, g_wl6);

    static cudaStream_t s1 = nullptr, s2 = nullptr;
    static cudaEvent_t eFork = nullptr, eS1 = nullptr, eS2 = nullptr;
    if (!s1) {
        cudaStreamCreateWithFlags(&s1, cudaStreamNonBlocking);
        cudaStreamCreateWithFlags(&s2, cudaStreamNonBlocking);
        cudaEventCreateWithFlags(&eFork, cudaEventDisableTiming);
        cudaEventCreateWithFlags(&eS1, cudaEventDisableTiming);
        cudaEventCreateWithFlags(&eS2, cudaEventDisableTiming);
    }

    const int gatI_smem = (P_ * 66 + 49 * P_ + 2 * P_ + 49 + 128) * 4;
    const int gatT_smem = (T_ * 66 + 64 * T_ + 2 * T_ + 64 + 128) * 4;
    cudaFuncSetAttribute(bf16_gemm_kernel, cudaFuncAttributeMaxDynamicSharedMemorySize, GEMM_SMEM);
    cudaFuncSetAttribute(attn_kernel, cudaFuncAttributeMaxDynamicSharedMemorySize, ATTN_SMEM);
    cudaFuncSetAttribute(gat_fused_kernel<P_, 49>, cudaFuncAttributeMaxDynamicSharedMemorySize, gatI_smem);
    cudaFuncSetAttribute(gat_fused_kernel<T_, 64>, cudaFuncAttributeMaxDynamicSharedMemorySize, gatT_smem);

    const size_t WSZ = (size_t)D_ * D_;
    const int WN4 = D_ * D_ / 4;                // 147456
    const int WGRID = (WN4 + 255) / 256;        // 576

    // ---- main stream pre-fork: zero + activation splits only ----
    zero3_kernel<<<(B_ * D_ + 255) / 256, 256>>>(p_tgf, p_igf, p_stok, B_ * D_, B_);
    split_kernel<<<(B_ * T_ * D_ / 4 + 255) / 256, 256>>>(text, p_th, p_tl, B_ * T_ * D_ / 4);
    split_kernel<<<(B_ * P_ * D_ / 4 + 255) / 256, 256>>>(image, p_ih, p_il, B_ * P_ * D_ / 4);
    cudaEventRecord(eFork, 0);
    cudaStreamWaitEvent(s1, eFork, 0);
    cudaStreamWaitEvent(s2, eFork, 0);

    // ---- s1: split wv,wq; GEMMs v (big), q (small) ----
    split_kernel<<<WGRID, 256, 0, s1>>>(wv, p_wh6 + 2 * WSZ, p_wl6 + 2 * WSZ, WN4);
    split_kernel<<<WGRID, 256, 0, s1>>>(wq, p_wh6 + 0 * WSZ, p_wl6 + 0 * WSZ, WN4);
    bf16_gemm_kernel<<<dim3(6, 49), 256, GEMM_SMEM, s1>>>(p_ih, p_il, p_wh6 + 2 * WSZ, p_wl6 + 2 * WSZ, bv, p_v, B_ * P_);
    bf16_gemm_kernel<<<dim3(6, 16), 256, GEMM_SMEM, s1>>>(p_th, p_tl, p_wh6 + 0 * WSZ, p_wl6 + 0 * WSZ, bq, p_q, B_ * T_);
    cudaEventRecord(eS1, s1);

    // ---- s2: split Wi,Wt; GEMMs whi (big), wht (small); GATs; cos ----
    split_kernel<<<WGRID, 256, 0, s2>>>(Wi, p_wh6 + 5 * WSZ, p_wl6 + 5 * WSZ, WN4);
    split_kernel<<<WGRID, 256, 0, s2>>>(Wt, p_wh6 + 4 * WSZ, p_wl6 + 4 * WSZ, WN4);
    bf16_gemm_kernel<<<dim3(6, 49), 256, GEMM_SMEM, s2>>>(p_ih, p_il, p_wh6 + 5 * WSZ, p_wl6 + 5 * WSZ, nullptr, p_whi, B_ * P_);
    bf16_gemm_kernel<<<dim3(6, 16), 256, GEMM_SMEM, s2>>>(p_th, p_tl, p_wh6 + 4 * WSZ, p_wl6 + 4 * WSZ, nullptr, p_wht, B_ * T_);
    gat_fused_kernel<T_, 64><<<dim3(1, H_, B_), 256, gatT_smem, s2>>>(p_wht, at, text_adj, T_ * T_, p_tgf);
    gat_fused_kernel<P_, 49><<<dim3(4, H_, B_), 256, gatI_smem, s2>>>(p_whi, ai, image_adj, 0, p_igf);
    cos_kernel<<<B_, 256, 0, s2>>>(p_tgf, p_igf, clip_text, clip_image, logit_sc, p_sphr, p_sglob);
    cudaEventRecord(eS2, s2);

    // ---- main: split wk,wo; k (big) -> attn -> upd -> tail ----
    split_kernel<<<WGRID, 256>>>(wk, p_wh6 + 1 * WSZ, p_wl6 + 1 * WSZ, WN4);
    split_kernel<<<WGRID, 256>>>(wo, p_wh6 + 3 * WSZ, p_wl6 + 3 * WSZ, WN4);
    bf16_gemm_kernel<<<dim3(6, 49), 256, GEMM_SMEM>>>(p_ih, p_il, p_wh6 + 1 * WSZ, p_wl6 + 1 * WSZ, bk, p_k, B_ * P_);
    cudaStreamWaitEvent((cudaStream_t)0, eS1, 0);
    attn_kernel<<<dim3(H_, B_), 256, ATTN_SMEM>>>(p_q, p_k, p_v, p_ath, p_atl);
    bf16_gemm_kernel<<<dim3(6, 16), 256, GEMM_SMEM>>>(p_ath, p_atl, p_wh6 + 3 * WSZ, p_wl6 + 3 * WSZ, bo, p_upd, B_ * T_);
    ftok_kernel<<<(B_ * D_) / 256, 256>>>(p_upd, p_ftok);
    stok_kernel<<<(B_ * T_ * 32) / 256, 256>>>(p_upd, image, p_stok);
    fglobal_kernel<<<dim3(6, B_), 128>>>(clip_text, Wp, bp, p_fglob);
    cudaStreamWaitEvent((cudaStream_t)0, eS2, 0);
    head_kernel<<<B_, 384>>>(p_stok, p_sphr, p_sglob, f1w, f1b, f2w, f2b,
                             p_ftok, p_tgf, p_fglob, c1w, c1b, c2w, c2b, out);
}